// round 11
// baseline (speedup 1.0000x reference)
#include <cuda_runtime.h>
#include <cuda_fp16.h>
#include <stdint.h>
#include <math.h>

typedef long long ll;
typedef unsigned int u32;
typedef unsigned long long u64;

static constexpr int B_   = 2;
static constexpr int S_   = 2048;
static constexpr int HID_ = 4096;
static constexpr int NH_  = 32;
static constexpr int G_   = 8;
static constexpr int RK_  = 256;
static constexpr int FGD_ = 256;
static constexpr int FH_  = 8192;

static constexpr ll N_H   = (ll)B_ * S_ * HID_;
static constexpr ll N_WQ  = (ll)HID_ * HID_;
static constexpr ll N_WVT = (ll)(G_*RK_) * HID_;
static constexpr ll N_WV  = (ll)(G_*FGD_) * HID_;
static constexpr ll N_U   = (ll)512 * (G_*RK_);
static constexpr ll N_WO  = (ll)HID_ * FH_;
static constexpr ll N_LAT = (ll)B_ * S_ * (G_*RK_);
static constexpr ll N_P   = (ll)B_ * NH_ * S_ * S_;
static constexpr ll N_SCR = (ll)B_ * S_ * FH_;

__device__ __half g_Hh[N_H],     g_Hl[N_H];
__device__ __half g_Wq1[N_WQ];
__device__ __half g_WVT1[N_WVT];
__device__ __half g_Wv1[N_WV];
__device__ __half g_U1[N_U];
__device__ __half g_Wo1[N_WO];
__device__ float  g_Qf[N_H],    g_Kf[N_H];
__device__ __half g_Qh[N_H], g_Ql[N_H], g_Kh[N_H], g_Kl[N_H];
__device__ __half g_klath[N_LAT], g_klatl[N_LAT];
__device__ float  g_vlatf[N_LAT];
__device__ __half g_vT1[N_LAT];
__device__ float  g_Pf[N_P];
__device__ __half g_Ph[N_P],     g_Pl[N_P];
__device__ __half g_scrh[N_SCR];

// ---------------- PTX helpers ----------------
__device__ __forceinline__ u32 smem_u32(const void* p) {
    u32 a;
    asm("{ .reg .u64 t; cvta.to.shared.u64 t, %1; cvt.u32.u64 %0, t; }" : "=r"(a) : "l"(p));
    return a;
}
__device__ __forceinline__ void cp16(u32 dst, const void* src) {
    asm volatile("cp.async.cg.shared.global [%0], [%1], 16;" :: "r"(dst), "l"(src));
}
__device__ __forceinline__ void cp_commit() { asm volatile("cp.async.commit_group;" ::: "memory"); }
template<int N>
__device__ __forceinline__ void cp_waitN() { asm volatile("cp.async.wait_group %0;" :: "n"(N) : "memory"); }
__device__ __forceinline__ void ldsm4(u32* r, u32 addr) {
    asm volatile("ldmatrix.sync.aligned.m8n8.x4.shared.b16 {%0,%1,%2,%3}, [%4];"
                 : "=r"(r[0]), "=r"(r[1]), "=r"(r[2]), "=r"(r[3]) : "r"(addr));
}
__device__ __forceinline__ void mma16816(float* d, const u32* a, const u32* b) {
    asm volatile("mma.sync.aligned.m16n8k16.row.col.f32.f16.f16.f32 "
                 "{%0,%1,%2,%3}, {%4,%5,%6,%7}, {%8,%9}, {%0,%1,%2,%3};"
                 : "+f"(d[0]), "+f"(d[1]), "+f"(d[2]), "+f"(d[3])
                 : "r"(a[0]), "r"(a[1]), "r"(a[2]), "r"(a[3]), "r"(b[0]), "r"(b[1]));
}
__device__ __forceinline__ u32 pack_hi(float v0, float v1) {
    __half2 p = __halves2half2(__float2half_rn(v0), __float2half_rn(v1));
    return *(u32*)&p;
}
__device__ __forceinline__ u32 pack_lo(float v0, float v1) {
    __half h0 = __float2half_rn(v0), h1 = __float2half_rn(v1);
    __half2 p = __halves2half2(__float2half_rn(v0 - __half2float(h0)),
                               __float2half_rn(v1 - __half2float(h1)));
    return *(u32*)&p;
}

// ======================================================================================
// warp-MMA fp16 GEMM, CTA tile 128x128, 8 warps (2x4), warp tile 64x32.
// 2 CTAs/SM (PREC 1/2; PREC 3 stays 1 CTA to avoid spills under the 128-reg cap).
//   PREC=1: A single fp16,  1 MMA/k-step, stage 16K, 5-deep
//   PREC=2: A hi/lo fp16,   2 MMAs/k-step, stage 24K, 4-deep
//   PREC=3: A hi/lo + B hi/lo, 3 MMAs/k-step, stage 32K, 3-deep
// MODE 0: f32 store  MODE 1: scores (scale+causal; skip masked tiles)
// MODE 2: AV (K truncation + PALU scramble; lo plane only if C1v!=null)
// MODE 3: fp16 plain store (hi, + lo if C1v)
// ======================================================================================
template<int MODE, int PREC>
__global__ void __launch_bounds__(256, PREC == 3 ? 1 : 2)
wgemm(const __half* __restrict__ Ah, const __half* __restrict__ Al,
      const __half* __restrict__ Bh, const __half* __restrict__ Bl,
      void* C0v, void* C1v, int K, int lda, int ldb, int ldc,
      ll aSo, ll aSi, ll bSo, ll bSi, ll cSo, ll cSi, int ziCount, float scale)
{
    constexpr int STAGE  = (PREC == 3) ? 32768 : (PREC == 2 ? 24576 : 16384);
    constexpr int NSTAGE = (PREC == 3) ? 3 : (PREC == 2 ? 4 : 5);
    constexpr int BOFF   = (PREC >= 2) ? 16384 : 8192;
    const int row0 = blockIdx.y * 128;
    const int col0 = blockIdx.x * 128;
    if (MODE == 1 && col0 > row0 + 127) return;

    const int zo = blockIdx.z / ziCount, zi = blockIdx.z % ziCount;
    const ll aOff = (ll)zo * aSo + (ll)zi * aSi + (ll)row0 * lda;
    const ll bOff = (ll)zo * bSo + (ll)zi * bSi + (ll)col0 * ldb;
    Ah += aOff; Bh += bOff;
    if (PREC >= 2) Al += aOff;
    if (PREC == 3) Bl += bOff;
    const ll cOff = (ll)zo * cSo + (ll)zi * cSi;

    int Keff = K;
    if (MODE == 2) { int lim = (row0 & 2047) + 128; if (lim < Keff) Keff = lim; }
    const int nK = Keff >> 5;

    extern __shared__ char sm[];
    const u32 sb = smem_u32(sm);
    const int tid = threadIdx.x, wid = tid >> 5, lane = tid & 31;
    const int wm = wid >> 2, wn = wid & 3;   // 2 x 4 warps, warp tile 64x32

    float acc[4][4][4];
    #pragma unroll
    for (int a = 0; a < 4; a++)
        #pragma unroll
        for (int b = 0; b < 4; b++)
            #pragma unroll
            for (int c = 0; c < 4; c++) acc[a][b][c] = 0.0f;

    auto load_stage = [&](int kt) {
        const u32 sbase = sb + (kt % NSTAGE) * STAGE;
        const int k0 = kt << 5;
        constexpr int NCHUNK = (PREC == 3) ? 8 : (PREC == 2 ? 6 : 4);
        constexpr int NA = (PREC >= 2) ? 1024 : 512;
        #pragma unroll
        for (int i = 0; i < NCHUNK; i++) {
            int idx = tid + i * 256;
            if (idx < NA) {                        // A: hi (and lo if PREC>=2)
                int sub = (PREC >= 2) ? (idx >> 9) : 0;
                int m = (PREC >= 2) ? (idx & 511) : idx;
                int r = m >> 2, c = m & 3;
                u32 d = sbase + sub * 8192 + r * 64 + (((c ^ (r & 3)) & 3) << 4);
                const __half* src = sub ? Al : Ah;
                cp16(d, src + (ll)r * lda + k0 + c * 8);
            } else {                               // B: 128 rows
                int j = idx - NA;
                int sub = (PREC == 3) ? (j >> 9) : 0;
                int m = (PREC == 3) ? (j & 511) : j;
                int r = m >> 2, c = m & 3;
                u32 d = sbase + BOFF + sub * 8192 + r * 64 + (((c ^ (r & 3)) & 3) << 4);
                const __half* src = (PREC == 3 && sub) ? Bl : Bh;
                cp16(d, src + (ll)r * ldb + k0 + c * 8);
            }
        }
    };

    #pragma unroll
    for (int s = 0; s < NSTAGE - 1; s++) {
        if (s == 0 || s < nK) load_stage(s);
        cp_commit();
    }

    for (int kt = 0; kt < nK; kt++) {
        if (kt + NSTAGE - 1 < nK) load_stage(kt + NSTAGE - 1);
        cp_commit();
        cp_waitN<NSTAGE - 1>();
        __syncthreads();

        const u32 abase = sb + (kt % NSTAGE) * STAGE;
        #pragma unroll
        for (int kk = 0; kk < 2; kk++) {
            u32 aH[4][4], aL[4][4];
            #pragma unroll
            for (int mi = 0; mi < 4; mi++) {
                int row = wm * 64 + mi * 16 + ((lane >> 3) & 1) * 8 + (lane & 7);
                int kb4 = kk * 2 + ((lane >> 4) & 1);
                u32 ad = abase + row * 64 + (((kb4 ^ (row & 3)) & 3) << 4);
                ldsm4(aH[mi], ad);
                if (PREC >= 2) ldsm4(aL[mi], ad + 8192);
            }
            #pragma unroll
            for (int nj = 0; nj < 2; nj++) {
                int n = wn * 32 + nj * 16 + ((lane >> 4) & 1) * 8 + (lane & 7);
                int kb4 = kk * 2 + ((lane >> 3) & 1);
                u32 bd = abase + BOFF + n * 64 + (((kb4 ^ (n & 3)) & 3) << 4);
                u32 tH[4];
                ldsm4(tH, bd);
                if (PREC == 3) {
                    u32 tL[4];
                    ldsm4(tL, bd + 8192);
                    #pragma unroll
                    for (int mi = 0; mi < 4; mi++) {
                        mma16816(acc[mi][nj*2],   aH[mi], tH);
                        mma16816(acc[mi][nj*2],   aH[mi], tL);
                        mma16816(acc[mi][nj*2],   aL[mi], tH);
                        mma16816(acc[mi][nj*2+1], aH[mi], tH + 2);
                        mma16816(acc[mi][nj*2+1], aH[mi], tL + 2);
                        mma16816(acc[mi][nj*2+1], aL[mi], tH + 2);
                    }
                } else if (PREC == 2) {
                    #pragma unroll
                    for (int mi = 0; mi < 4; mi++) {
                        mma16816(acc[mi][nj*2],   aH[mi], tH);
                        mma16816(acc[mi][nj*2],   aL[mi], tH);
                        mma16816(acc[mi][nj*2+1], aH[mi], tH + 2);
                        mma16816(acc[mi][nj*2+1], aL[mi], tH + 2);
                    }
                } else {
                    #pragma unroll
                    for (int mi = 0; mi < 4; mi++) {
                        mma16816(acc[mi][nj*2],   aH[mi], tH);
                        mma16816(acc[mi][nj*2+1], aH[mi], tH + 2);
                    }
                }
            }
        }
        __syncthreads();
    }

    // ---- epilogue ----
    const int g = lane >> 2, tig = lane & 3;
    #pragma unroll
    for (int mi = 0; mi < 4; mi++) {
        #pragma unroll
        for (int ni = 0; ni < 4; ni++) {
            int r1 = row0 + wm * 64 + mi * 16 + g;
            int r2 = r1 + 8;
            int col = col0 + wn * 32 + ni * 8 + tig * 2;
            float* ac = acc[mi][ni];
            if (MODE == 0) {
                float* C = (float*)C0v + cOff;
                *(float2*)(C + (ll)r1 * ldc + col) = make_float2(ac[0], ac[1]);
                *(float2*)(C + (ll)r2 * ldc + col) = make_float2(ac[2], ac[3]);
            } else if (MODE == 1) {
                float* C = (float*)C0v + cOff;
                float2 v1, v2;
                v1.x = (col     > r1) ? -1e30f : ac[0] * scale;
                v1.y = (col + 1 > r1) ? -1e30f : ac[1] * scale;
                v2.x = (col     > r2) ? -1e30f : ac[2] * scale;
                v2.y = (col + 1 > r2) ? -1e30f : ac[3] * scale;
                *(float2*)(C + (ll)r1 * ldc + col) = v1;
                *(float2*)(C + (ll)r2 * ldc + col) = v2;
            } else {
                __half* Ch = (__half*)C0v;
                __half* Cl = (__half*)C1v;
                ll b1, b2;
                if (MODE == 3) {
                    b1 = cOff + (ll)r1 * ldc + col;
                    b2 = cOff + (ll)r2 * ldc + col;
                } else {
                    int hg1 = r1 >> 11, s1 = r1 & 2047;
                    int hg2 = r2 >> 11, s2 = r2 & 2047;
                    b1 = cOff + (ll)(hg1 * 512 + (s1 >> 2)) * FH_ + (ll)(s1 & 3) * 2048 + col;
                    b2 = cOff + (ll)(hg2 * 512 + (s2 >> 2)) * FH_ + (ll)(s2 & 3) * 2048 + col;
                }
                *(u32*)(Ch + b1) = pack_hi(ac[0], ac[1]);
                *(u32*)(Ch + b2) = pack_hi(ac[2], ac[3]);
                if (Cl) {
                    *(u32*)(Cl + b1) = pack_lo(ac[0], ac[1]);
                    *(u32*)(Cl + b2) = pack_lo(ac[2], ac[3]);
                }
            }
        }
    }
}

// ============ mega-convert: all fp32 -> fp16 conversions in ONE launch ============
static constexpr ll C_H   = N_H   / 4;
static constexpr ll C_WQ  = C_H   + N_WQ  / 4;
static constexpr ll C_WVT = C_WQ  + N_WVT / 4;
static constexpr ll C_WV  = C_WVT + N_WV  / 4;
static constexpr ll C_U   = C_WV  + N_U   / 4;
static constexpr ll C_WO  = C_U   + N_WO  / 4;

__global__ void convert_all(const float* __restrict__ H,  const float* __restrict__ Wq,
                            const float* __restrict__ WVT, const float* __restrict__ Wv,
                            const float* __restrict__ U,  const float* __restrict__ Wo,
                            __half* __restrict__ Hh, __half* __restrict__ Hl,
                            __half* __restrict__ Wq1, __half* __restrict__ WVT1,
                            __half* __restrict__ Wv1, __half* __restrict__ U1,
                            __half* __restrict__ Wo1)
{
    ll i = (ll)blockIdx.x * blockDim.x + threadIdx.x;
    const ll stride = (ll)gridDim.x * blockDim.x;
    for (; i < C_WO; i += stride) {
        const float* src; __half* dh; __half* dl = nullptr; ll j;
        if (i < C_H)        { src = H;   dh = Hh;   dl = Hl; j = i; }
        else if (i < C_WQ)  { src = Wq;  dh = Wq1;  j = i - C_H; }
        else if (i < C_WVT) { src = WVT; dh = WVT1; j = i - C_WQ; }
        else if (i < C_WV)  { src = Wv;  dh = Wv1;  j = i - C_WVT; }
        else if (i < C_U)   { src = U;   dh = U1;   j = i - C_WV; }
        else                { src = Wo;  dh = Wo1;  j = i - C_U; }
        float4 v = __ldg((const float4*)src + j);
        ((uint2*)dh)[j] = make_uint2(pack_hi(v.x, v.y), pack_hi(v.z, v.w));
        if (dl) ((uint2*)dl)[j] = make_uint2(pack_lo(v.x, v.y), pack_lo(v.z, v.w));
    }
}

// ============ RoPE: fp32 Q/K -> rotated (hi,lo) fp16 ============
__global__ void rope_split(const float* __restrict__ Qf, const float* __restrict__ Kf,
                           const int* __restrict__ pos,
                           __half* __restrict__ Qh, __half* __restrict__ Ql,
                           __half* __restrict__ Kh, __half* __restrict__ Kl)
{
    const int row = blockIdx.x;
    const float p = (float)__ldg(pos + row);
    const ll base = (ll)row * HID_;
    for (int t = threadIdx.x; t < NH_ * 64; t += blockDim.x) {
        int h = t >> 6, d = t & 63;
        float inv = exp2f(-(float)d * (13.287712379549449f / 64.0f));
        float sn, cs;
        sincosf(p * inv, &sn, &cs);
        ll c1 = base + h * 128 + d, c2 = c1 + 64;
        float qx = Qf[c1], qy = Qf[c2];
        float q1 = qx * cs - qy * sn, q2 = qy * cs + qx * sn;
        __half a = __float2half_rn(q1); Qh[c1] = a; Ql[c1] = __float2half_rn(q1 - __half2float(a));
        __half b = __float2half_rn(q2); Qh[c2] = b; Ql[c2] = __float2half_rn(q2 - __half2float(b));
        float kx = Kf[c1], ky = Kf[c2];
        float k1 = kx * cs - ky * sn, k2 = ky * cs + kx * sn;
        __half c = __float2half_rn(k1); Kh[c1] = c; Kl[c1] = __float2half_rn(k1 - __half2float(c));
        __half e = __float2half_rn(k2); Kh[c2] = e; Kl[c2] = __float2half_rn(k2 - __half2float(e));
    }
}

// ============ transpose: vlat[b*2048+s][2048] -> vT[b*2048+n][s] single fp16 ============
__global__ void transpose_single(const float* __restrict__ V, __half* __restrict__ Th)
{
    __shared__ float t[32][33];
    const int b = blockIdx.z, s0 = blockIdx.x * 32, n0 = blockIdx.y * 32;
    const int x = threadIdx.x;
    for (int y = threadIdx.y; y < 32; y += 8)
        t[y][x] = __ldg(V + (ll)(b * 2048 + s0 + y) * 2048 + n0 + x);
    __syncthreads();
    for (int yo = threadIdx.y; yo < 32; yo += 8) {
        ll idx = (ll)(b * 2048 + n0 + yo) * 2048 + s0 + x;
        Th[idx] = __float2half_rn(t[x][yo]);
    }
}

// ============ causal-prefix softmax: fp32 logits -> (hi,lo) fp16 probs ============
__global__ void __launch_bounds__(256) softmax_split(const float* __restrict__ Pf,
                                                     __half* __restrict__ Ph, __half* __restrict__ Pl)
{
    const ll row = blockIdx.x;
    const int rl = (int)(row & 2047);
    const int nproc = ((rl >> 7) + 1) << 7;
    const float* src = Pf + row * 2048;
    const int tid = threadIdx.x;
    float v[8];
    float m = -1e38f;
    #pragma unroll
    for (int i = 0; i < 8; i++) {
        int c = tid + i * 256;
        v[i] = (c < nproc) ? src[c] : -1e38f;
        m = fmaxf(m, v[i]);
    }
    __shared__ float red[256];
    red[tid] = m; __syncthreads();
    #pragma unroll
    for (int s = 128; s > 0; s >>= 1) {
        if (tid < s) red[tid] = fmaxf(red[tid], red[tid + s]);
        __syncthreads();
    }
    m = red[0];
    __syncthreads();
    float sum = 0.0f;
    #pragma unroll
    for (int i = 0; i < 8; i++) { v[i] = expf(v[i] - m); sum += v[i]; }
    red[tid] = sum; __syncthreads();
    #pragma unroll
    for (int s = 128; s > 0; s >>= 1) {
        if (tid < s) red[tid] += red[tid + s];
        __syncthreads();
    }
    const float inv = 1.0f / red[0];
    #pragma unroll
    for (int i = 0; i < 8; i++) {
        int c = tid + i * 256;
        if (c < nproc) {
            float pr = v[i] * inv;
            __half h = __float2half_rn(pr);
            Ph[row * 2048 + c] = h;
            Pl[row * 2048 + c] = __float2half_rn(pr - __half2float(h));
        }
    }
}

// ============ launcher ============
extern "C" void kernel_launch(void* const* d_in, const int* in_sizes, int n_in,
                              void* d_out, int out_size)
{
    const float* H   = (const float*)d_in[0];
    const int*   pos = (const int*)  d_in[2];
    const float* Wq  = (const float*)d_in[3];
    const float* WVT = (const float*)d_in[4];
    const float* U   = (const float*)d_in[5];
    const float* Wv  = (const float*)d_in[6];
    const float* Wo  = (const float*)d_in[7];
    float* out = (float*)d_out;

    const int SMEM1 = 5 * 16384;    // PREC=1: 80K/CTA, 2 CTAs -> 160K
    const int SMEM2 = 4 * 24576;    // PREC=2: 96K/CTA, 2 CTAs -> 192K
    const int SMEM3 = 3 * 32768;    // PREC=3: 96K/CTA, 1 CTA
    cudaFuncSetAttribute((const void*)wgemm<0,2>, cudaFuncAttributeMaxDynamicSharedMemorySize, SMEM2);
    cudaFuncSetAttribute((const void*)wgemm<0,1>, cudaFuncAttributeMaxDynamicSharedMemorySize, SMEM1);
    cudaFuncSetAttribute((const void*)wgemm<1,3>, cudaFuncAttributeMaxDynamicSharedMemorySize, SMEM3);
    cudaFuncSetAttribute((const void*)wgemm<2,2>, cudaFuncAttributeMaxDynamicSharedMemorySize, SMEM2);
    cudaFuncSetAttribute((const void*)wgemm<3,2>, cudaFuncAttributeMaxDynamicSharedMemorySize, SMEM2);

    __half *Hh, *Hl, *Wq1, *WVT1, *Wv1, *U1, *Wo1;
    __half *Qh, *Ql, *Kh, *Kl, *klath, *klatl, *vT1, *Ph, *Pl, *scrh;
    float *Qf, *Kf, *vlatf, *Pf;
    cudaGetSymbolAddress((void**)&Hh, g_Hh);       cudaGetSymbolAddress((void**)&Hl, g_Hl);
    cudaGetSymbolAddress((void**)&Wq1, g_Wq1);
    cudaGetSymbolAddress((void**)&WVT1, g_WVT1);
    cudaGetSymbolAddress((void**)&Wv1, g_Wv1);
    cudaGetSymbolAddress((void**)&U1, g_U1);
    cudaGetSymbolAddress((void**)&Wo1, g_Wo1);
    cudaGetSymbolAddress((void**)&Qf, g_Qf);       cudaGetSymbolAddress((void**)&Kf, g_Kf);
    cudaGetSymbolAddress((void**)&Qh, g_Qh);       cudaGetSymbolAddress((void**)&Ql, g_Ql);
    cudaGetSymbolAddress((void**)&Kh, g_Kh);       cudaGetSymbolAddress((void**)&Kl, g_Kl);
    cudaGetSymbolAddress((void**)&klath, g_klath); cudaGetSymbolAddress((void**)&klatl, g_klatl);
    cudaGetSymbolAddress((void**)&vlatf, g_vlatf);
    cudaGetSymbolAddress((void**)&vT1, g_vT1);
    cudaGetSymbolAddress((void**)&Pf, g_Pf);
    cudaGetSymbolAddress((void**)&Ph, g_Ph);       cudaGetSymbolAddress((void**)&Pl, g_Pl);
    cudaGetSymbolAddress((void**)&scrh, g_scrh);

    // our launch 0: ALL converts in one kernel
    convert_all<<<8192, 256>>>(H, Wq, WVT, Wv, U, Wo, Hh, Hl, Wq1, WVT1, Wv1, U1, Wo1);

    // our launch 1: klat = H @ WVT^T (4096x2048) -> fp16 hi/lo
    wgemm<3,2><<<dim3(16, 32, 1), 256, SMEM2>>>(
        Hh, Hl, WVT1, nullptr, klath, klatl, HID_, HID_, HID_, 2048,
        0, 0, 0, 0, 0, 0, 1, 1.0f);
    // our launch 2: vlat = H @ Wv^T (4096x2048) -> fp32
    wgemm<0,2><<<dim3(16, 32, 1), 256, SMEM2>>>(
        Hh, Hl, Wv1, nullptr, vlatf, nullptr, HID_, HID_, HID_, 2048,
        0, 0, 0, 0, 0, 0, 1, 1.0f);
    // our launch 3: Q = H @ Wq^T (4096x4096, K=4096) -> fp32   [ncu target if prepend=2]
    wgemm<0,2><<<dim3(32, 32, 1), 256, SMEM2>>>(
        Hh, Hl, Wq1, nullptr, Qf, nullptr, HID_, HID_, HID_, HID_,
        0, 0, 0, 0, 0, 0, 1, 1.0f);
    // our launch 4: K recon per (b,g): (2048x512, K=256) -> fp32  [ncu target if prepend=1]
    wgemm<0,2><<<dim3(4, 16, 16), 256, SMEM2>>>(
        klath, klatl, U1, nullptr, Kf, nullptr, RK_, 2048, 2048, HID_,
        (ll)S_ * 2048, RK_, 0, RK_, (ll)S_ * HID_, 512, G_, 1.0f);
    // our launch 5: vT transpose
    transpose_single<<<dim3(64, 64, B_), dim3(32, 8)>>>(vlatf, vT1);
    // our launch 6: RoPE -> hi/lo fp16 Q, K
    rope_split<<<B_ * S_, 256>>>(Qf, Kf, pos, Qh, Ql, Kh, Kl);
    // our launch 7: scores per (b,h): (2048x2048, K=128), 3-term, scale+causal -> fp32
    wgemm<1,3><<<dim3(16, 16, 64), 256, SMEM3>>>(
        Qh, Ql, Kh, Kl, Pf, nullptr, 128, HID_, HID_, S_,
        (ll)S_ * HID_, 128, (ll)S_ * HID_, 128,
        (ll)NH_ * S_ * S_, (ll)S_ * S_, NH_, 0.08838834764831845f);
    // our launch 8: softmax -> fp16 hi/lo probs (causal prefix only)
    softmax_split<<<B_ * NH_ * S_, 256>>>(Pf, Ph, Pl);
    // our launch 9: AV per (b,g): (8192x256, K truncated) -> scrambled fp16 (hi only)
    wgemm<2,2><<<dim3(2, 64, 16), 256, SMEM2>>>(
        Ph, Pl, vT1, nullptr, scrh, nullptr, S_, S_, S_, 0,
        (ll)NH_ * S_ * S_, (ll)4 * S_ * S_,
        (ll)2048 * 2048, (ll)FGD_ * S_,
        (ll)S_ * FH_, FGD_, G_, 1.0f);
    // our launch 10: out = scr @ Wo^T (4096x4096, K=8192), A single fp16
    wgemm<0,1><<<dim3(32, 32, 1), 256, SMEM1>>>(
        scrh, nullptr, Wo1, nullptr, out, nullptr, FH_, FH_, FH_, HID_,
        0, 0, 0, 0, 0, 0, 1, 1.0f);
}

// round 12
// speedup vs baseline: 1.1782x; 1.1782x over previous
#include <cuda_runtime.h>
#include <cuda_fp16.h>
#include <stdint.h>
#include <math.h>

typedef long long ll;
typedef unsigned int u32;
typedef unsigned long long u64;

static constexpr int B_   = 2;
static constexpr int S_   = 2048;
static constexpr int HID_ = 4096;
static constexpr int NH_  = 32;
static constexpr int G_   = 8;
static constexpr int RK_  = 256;
static constexpr int FGD_ = 256;
static constexpr int FH_  = 8192;

static constexpr ll N_H   = (ll)B_ * S_ * HID_;
static constexpr ll N_WQ  = (ll)HID_ * HID_;
static constexpr ll N_WVT = (ll)(G_*RK_) * HID_;
static constexpr ll N_WV  = (ll)(G_*FGD_) * HID_;
static constexpr ll N_U   = (ll)512 * (G_*RK_);
static constexpr ll N_WO  = (ll)HID_ * FH_;
static constexpr ll N_LAT = (ll)B_ * S_ * (G_*RK_);
static constexpr ll N_P   = (ll)B_ * NH_ * S_ * S_;
static constexpr ll N_SCR = (ll)B_ * S_ * FH_;

__device__ __half g_Hh[N_H],     g_Hl[N_H];
__device__ __half g_Wq1[N_WQ];
__device__ __half g_WVT1[N_WVT];
__device__ __half g_Wv1[N_WV];
__device__ __half g_U1[N_U];
__device__ __half g_Wo1[N_WO];
__device__ float  g_Qf[N_H],    g_Kf[N_H];
__device__ __half g_Qh[N_H], g_Ql[N_H], g_Kh[N_H], g_Kl[N_H];
__device__ __half g_klath[N_LAT], g_klatl[N_LAT];
__device__ float  g_vlatf[N_LAT];
__device__ __half g_vT1[N_LAT];
__device__ float  g_Pf[N_P];
__device__ __half g_Ph[N_P],     g_Pl[N_P];
__device__ __half g_scrh[N_SCR];

// ---------------- PTX helpers ----------------
__device__ __forceinline__ u32 smem_u32(const void* p) {
    u32 a;
    asm("{ .reg .u64 t; cvta.to.shared.u64 t, %1; cvt.u32.u64 %0, t; }" : "=r"(a) : "l"(p));
    return a;
}
__device__ __forceinline__ void cp16(u32 dst, const void* src) {
    asm volatile("cp.async.cg.shared.global [%0], [%1], 16;" :: "r"(dst), "l"(src));
}
__device__ __forceinline__ void cp_commit() { asm volatile("cp.async.commit_group;" ::: "memory"); }
template<int N>
__device__ __forceinline__ void cp_waitN() { asm volatile("cp.async.wait_group %0;" :: "n"(N) : "memory"); }
__device__ __forceinline__ void ldsm4(u32* r, u32 addr) {
    asm volatile("ldmatrix.sync.aligned.m8n8.x4.shared.b16 {%0,%1,%2,%3}, [%4];"
                 : "=r"(r[0]), "=r"(r[1]), "=r"(r[2]), "=r"(r[3]) : "r"(addr));
}
__device__ __forceinline__ void mma16816(float* d, const u32* a, const u32* b) {
    asm volatile("mma.sync.aligned.m16n8k16.row.col.f32.f16.f16.f32 "
                 "{%0,%1,%2,%3}, {%4,%5,%6,%7}, {%8,%9}, {%0,%1,%2,%3};"
                 : "+f"(d[0]), "+f"(d[1]), "+f"(d[2]), "+f"(d[3])
                 : "r"(a[0]), "r"(a[1]), "r"(a[2]), "r"(a[3]), "r"(b[0]), "r"(b[1]));
}
__device__ __forceinline__ u32 pack_hi(float v0, float v1) {
    __half2 p = __halves2half2(__float2half_rn(v0), __float2half_rn(v1));
    return *(u32*)&p;
}
__device__ __forceinline__ u32 pack_lo(float v0, float v1) {
    __half h0 = __float2half_rn(v0), h1 = __float2half_rn(v1);
    __half2 p = __halves2half2(__float2half_rn(v0 - __half2float(h0)),
                               __float2half_rn(v1 - __half2float(h1)));
    return *(u32*)&p;
}
// conflict-free 16B-slot swizzle for 64B rows: slot distinct over any 8-row window
__device__ __forceinline__ u32 swz(int r, int c) {
    return (u32)(r * 64 + (((c ^ ((r >> 1) & 3)) & 3) << 4));
}

// ======================================================================================
// warp-MMA fp16 GEMM, CTA tile 128x128, 8 warps (2x4), warp tile 64x32, 2 CTAs/SM.
//   PREC=1: A single fp16,  1 MMA/k-step, stage 16K, 5-deep
//   PREC=2: A hi/lo fp16,   2 MMAs/k-step, stage 24K, 4-deep
//   PREC=3: A hi/lo + B hi/lo, 3 MMAs/k-step, stage 32K, 3-deep (1 CTA/SM)
// MODE 0: f32 store  MODE 1: scores (scale+causal; skip masked tiles)
// MODE 2: AV (K truncation + PALU scramble; lo plane only if C1v!=null)
// MODE 3: fp16 plain store (hi, + lo if C1v)
// ======================================================================================
template<int MODE, int PREC>
__global__ void __launch_bounds__(256, PREC == 3 ? 1 : 2)
wgemm(const __half* __restrict__ Ah, const __half* __restrict__ Al,
      const __half* __restrict__ Bh, const __half* __restrict__ Bl,
      void* C0v, void* C1v, int K, int lda, int ldb, int ldc,
      ll aSo, ll aSi, ll bSo, ll bSi, ll cSo, ll cSi, int ziCount, float scale)
{
    constexpr int STAGE  = (PREC == 3) ? 32768 : (PREC == 2 ? 24576 : 16384);
    constexpr int NSTAGE = (PREC == 3) ? 3 : (PREC == 2 ? 4 : 5);
    constexpr int BOFF   = (PREC >= 2) ? 16384 : 8192;
    const int row0 = blockIdx.y * 128;
    const int col0 = blockIdx.x * 128;
    if (MODE == 1 && col0 > row0 + 127) return;

    const int zo = blockIdx.z / ziCount, zi = blockIdx.z % ziCount;
    const ll aOff = (ll)zo * aSo + (ll)zi * aSi + (ll)row0 * lda;
    const ll bOff = (ll)zo * bSo + (ll)zi * bSi + (ll)col0 * ldb;
    Ah += aOff; Bh += bOff;
    if (PREC >= 2) Al += aOff;
    if (PREC == 3) Bl += bOff;
    const ll cOff = (ll)zo * cSo + (ll)zi * cSi;

    int Keff = K;
    if (MODE == 2) { int lim = (row0 & 2047) + 128; if (lim < Keff) Keff = lim; }
    const int nK = Keff >> 5;

    extern __shared__ char sm[];
    const u32 sb = smem_u32(sm);
    const int tid = threadIdx.x, wid = tid >> 5, lane = tid & 31;
    const int wm = wid >> 2, wn = wid & 3;

    float acc[4][4][4];
    #pragma unroll
    for (int a = 0; a < 4; a++)
        #pragma unroll
        for (int b = 0; b < 4; b++)
            #pragma unroll
            for (int c = 0; c < 4; c++) acc[a][b][c] = 0.0f;

    auto load_stage = [&](int kt) {
        const u32 sbase = sb + (kt % NSTAGE) * STAGE;
        const int k0 = kt << 5;
        constexpr int NCHUNK = (PREC == 3) ? 8 : (PREC == 2 ? 6 : 4);
        constexpr int NA = (PREC >= 2) ? 1024 : 512;
        #pragma unroll
        for (int i = 0; i < NCHUNK; i++) {
            int idx = tid + i * 256;
            if (idx < NA) {                        // A: hi (and lo if PREC>=2)
                int sub = (PREC >= 2) ? (idx >> 9) : 0;
                int m = (PREC >= 2) ? (idx & 511) : idx;
                int r = m >> 2, c = m & 3;
                u32 d = sbase + sub * 8192 + swz(r, c);
                const __half* src = sub ? Al : Ah;
                cp16(d, src + (ll)r * lda + k0 + c * 8);
            } else {                               // B: 128 rows
                int j = idx - NA;
                int sub = (PREC == 3) ? (j >> 9) : 0;
                int m = (PREC == 3) ? (j & 511) : j;
                int r = m >> 2, c = m & 3;
                u32 d = sbase + BOFF + sub * 8192 + swz(r, c);
                const __half* src = (PREC == 3 && sub) ? Bl : Bh;
                cp16(d, src + (ll)r * ldb + k0 + c * 8);
            }
        }
    };

    #pragma unroll
    for (int s = 0; s < NSTAGE - 1; s++) {
        if (s == 0 || s < nK) load_stage(s);
        cp_commit();
    }

    for (int kt = 0; kt < nK; kt++) {
        if (kt + NSTAGE - 1 < nK) load_stage(kt + NSTAGE - 1);
        cp_commit();
        cp_waitN<NSTAGE - 1>();
        __syncthreads();

        const u32 abase = sb + (kt % NSTAGE) * STAGE;
        #pragma unroll
        for (int kk = 0; kk < 2; kk++) {
            u32 aH[4][4], aL[4][4];
            #pragma unroll
            for (int mi = 0; mi < 4; mi++) {
                int row = wm * 64 + mi * 16 + ((lane >> 3) & 1) * 8 + (lane & 7);
                int kb4 = kk * 2 + ((lane >> 4) & 1);
                u32 ad = abase + swz(row, kb4);
                ldsm4(aH[mi], ad);
                if (PREC >= 2) ldsm4(aL[mi], ad + 8192);
            }
            #pragma unroll
            for (int nj = 0; nj < 2; nj++) {
                int n = wn * 32 + nj * 16 + ((lane >> 4) & 1) * 8 + (lane & 7);
                int kb4 = kk * 2 + ((lane >> 3) & 1);
                u32 bd = abase + BOFF + swz(n, kb4);
                u32 tH[4];
                ldsm4(tH, bd);
                if (PREC == 3) {
                    u32 tL[4];
                    ldsm4(tL, bd + 8192);
                    #pragma unroll
                    for (int mi = 0; mi < 4; mi++) {
                        mma16816(acc[mi][nj*2],   aH[mi], tH);
                        mma16816(acc[mi][nj*2],   aH[mi], tL);
                        mma16816(acc[mi][nj*2],   aL[mi], tH);
                        mma16816(acc[mi][nj*2+1], aH[mi], tH + 2);
                        mma16816(acc[mi][nj*2+1], aH[mi], tL + 2);
                        mma16816(acc[mi][nj*2+1], aL[mi], tH + 2);
                    }
                } else if (PREC == 2) {
                    #pragma unroll
                    for (int mi = 0; mi < 4; mi++) {
                        mma16816(acc[mi][nj*2],   aH[mi], tH);
                        mma16816(acc[mi][nj*2],   aL[mi], tH);
                        mma16816(acc[mi][nj*2+1], aH[mi], tH + 2);
                        mma16816(acc[mi][nj*2+1], aL[mi], tH + 2);
                    }
                } else {
                    #pragma unroll
                    for (int mi = 0; mi < 4; mi++) {
                        mma16816(acc[mi][nj*2],   aH[mi], tH);
                        mma16816(acc[mi][nj*2+1], aH[mi], tH + 2);
                    }
                }
            }
        }
        __syncthreads();
    }

    // ---- epilogue ----
    const int g = lane >> 2, tig = lane & 3;
    #pragma unroll
    for (int mi = 0; mi < 4; mi++) {
        #pragma unroll
        for (int ni = 0; ni < 4; ni++) {
            int r1 = row0 + wm * 64 + mi * 16 + g;
            int r2 = r1 + 8;
            int col = col0 + wn * 32 + ni * 8 + tig * 2;
            float* ac = acc[mi][ni];
            if (MODE == 0) {
                float* C = (float*)C0v + cOff;
                *(float2*)(C + (ll)r1 * ldc + col) = make_float2(ac[0], ac[1]);
                *(float2*)(C + (ll)r2 * ldc + col) = make_float2(ac[2], ac[3]);
            } else if (MODE == 1) {
                float* C = (float*)C0v + cOff;
                float2 v1, v2;
                v1.x = (col     > r1) ? -1e30f : ac[0] * scale;
                v1.y = (col + 1 > r1) ? -1e30f : ac[1] * scale;
                v2.x = (col     > r2) ? -1e30f : ac[2] * scale;
                v2.y = (col + 1 > r2) ? -1e30f : ac[3] * scale;
                *(float2*)(C + (ll)r1 * ldc + col) = v1;
                *(float2*)(C + (ll)r2 * ldc + col) = v2;
            } else {
                __half* Ch = (__half*)C0v;
                __half* Cl = (__half*)C1v;
                ll b1, b2;
                if (MODE == 3) {
                    b1 = cOff + (ll)r1 * ldc + col;
                    b2 = cOff + (ll)r2 * ldc + col;
                } else {
                    int hg1 = r1 >> 11, s1 = r1 & 2047;
                    int hg2 = r2 >> 11, s2 = r2 & 2047;
                    b1 = cOff + (ll)(hg1 * 512 + (s1 >> 2)) * FH_ + (ll)(s1 & 3) * 2048 + col;
                    b2 = cOff + (ll)(hg2 * 512 + (s2 >> 2)) * FH_ + (ll)(s2 & 3) * 2048 + col;
                }
                *(u32*)(Ch + b1) = pack_hi(ac[0], ac[1]);
                *(u32*)(Ch + b2) = pack_hi(ac[2], ac[3]);
                if (Cl) {
                    *(u32*)(Cl + b1) = pack_lo(ac[0], ac[1]);
                    *(u32*)(Cl + b2) = pack_lo(ac[2], ac[3]);
                }
            }
        }
    }
}

// ============ mega-convert: all fp32 -> fp16 conversions in ONE launch ============
static constexpr ll C_H   = N_H   / 4;
static constexpr ll C_WQ  = C_H   + N_WQ  / 4;
static constexpr ll C_WVT = C_WQ  + N_WVT / 4;
static constexpr ll C_WV  = C_WVT + N_WV  / 4;
static constexpr ll C_U   = C_WV  + N_U   / 4;
static constexpr ll C_WO  = C_U   + N_WO  / 4;

__global__ void convert_all(const float* __restrict__ H,  const float* __restrict__ Wq,
                            const float* __restrict__ WVT, const float* __restrict__ Wv,
                            const float* __restrict__ U,  const float* __restrict__ Wo,
                            __half* __restrict__ Hh, __half* __restrict__ Hl,
                            __half* __restrict__ Wq1, __half* __restrict__ WVT1,
                            __half* __restrict__ Wv1, __half* __restrict__ U1,
                            __half* __restrict__ Wo1)
{
    ll i = (ll)blockIdx.x * blockDim.x + threadIdx.x;
    const ll stride = (ll)gridDim.x * blockDim.x;
    for (; i < C_WO; i += stride) {
        const float* src; __half* dh; __half* dl = nullptr; ll j;
        if (i < C_H)        { src = H;   dh = Hh;   dl = Hl; j = i; }
        else if (i < C_WQ)  { src = Wq;  dh = Wq1;  j = i - C_H; }
        else if (i < C_WVT) { src = WVT; dh = WVT1; j = i - C_WQ; }
        else if (i < C_WV)  { src = Wv;  dh = Wv1;  j = i - C_WVT; }
        else if (i < C_U)   { src = U;   dh = U1;   j = i - C_WV; }
        else                { src = Wo;  dh = Wo1;  j = i - C_U; }
        float4 v = __ldg((const float4*)src + j);
        ((uint2*)dh)[j] = make_uint2(pack_hi(v.x, v.y), pack_hi(v.z, v.w));
        if (dl) ((uint2*)dl)[j] = make_uint2(pack_lo(v.x, v.y), pack_lo(v.z, v.w));
    }
}

// ============ RoPE: fp32 Q/K -> rotated (hi,lo) fp16 ============
__global__ void rope_split(const float* __restrict__ Qf, const float* __restrict__ Kf,
                           const int* __restrict__ pos,
                           __half* __restrict__ Qh, __half* __restrict__ Ql,
                           __half* __restrict__ Kh, __half* __restrict__ Kl)
{
    const int row = blockIdx.x;
    const float p = (float)__ldg(pos + row);
    const ll base = (ll)row * HID_;
    for (int t = threadIdx.x; t < NH_ * 64; t += blockDim.x) {
        int h = t >> 6, d = t & 63;
        float inv = exp2f(-(float)d * (13.287712379549449f / 64.0f));
        float sn, cs;
        sincosf(p * inv, &sn, &cs);
        ll c1 = base + h * 128 + d, c2 = c1 + 64;
        float qx = Qf[c1], qy = Qf[c2];
        float q1 = qx * cs - qy * sn, q2 = qy * cs + qx * sn;
        __half a = __float2half_rn(q1); Qh[c1] = a; Ql[c1] = __float2half_rn(q1 - __half2float(a));
        __half b = __float2half_rn(q2); Qh[c2] = b; Ql[c2] = __float2half_rn(q2 - __half2float(b));
        float kx = Kf[c1], ky = Kf[c2];
        float k1 = kx * cs - ky * sn, k2 = ky * cs + kx * sn;
        __half c = __float2half_rn(k1); Kh[c1] = c; Kl[c1] = __float2half_rn(k1 - __half2float(c));
        __half e = __float2half_rn(k2); Kh[c2] = e; Kl[c2] = __float2half_rn(k2 - __half2float(e));
    }
}

// ============ transpose: vlat[b*2048+s][2048] -> vT[b*2048+n][s] single fp16 ============
__global__ void transpose_single(const float* __restrict__ V, __half* __restrict__ Th)
{
    __shared__ float t[32][33];
    const int b = blockIdx.z, s0 = blockIdx.x * 32, n0 = blockIdx.y * 32;
    const int x = threadIdx.x;
    for (int y = threadIdx.y; y < 32; y += 8)
        t[y][x] = __ldg(V + (ll)(b * 2048 + s0 + y) * 2048 + n0 + x);
    __syncthreads();
    for (int yo = threadIdx.y; yo < 32; yo += 8) {
        ll idx = (ll)(b * 2048 + n0 + yo) * 2048 + s0 + x;
        Th[idx] = __float2half_rn(t[x][yo]);
    }
}

// ============ causal-prefix softmax: fp32 logits -> (hi,lo) fp16 probs ============
__global__ void __launch_bounds__(256) softmax_split(const float* __restrict__ Pf,
                                                     __half* __restrict__ Ph, __half* __restrict__ Pl)
{
    const ll row = blockIdx.x;
    const int rl = (int)(row & 2047);
    const int nproc = ((rl >> 7) + 1) << 7;
    const float* src = Pf + row * 2048;
    const int tid = threadIdx.x;
    float v[8];
    float m = -1e38f;
    #pragma unroll
    for (int i = 0; i < 8; i++) {
        int c = tid + i * 256;
        v[i] = (c < nproc) ? src[c] : -1e38f;
        m = fmaxf(m, v[i]);
    }
    __shared__ float red[256];
    red[tid] = m; __syncthreads();
    #pragma unroll
    for (int s = 128; s > 0; s >>= 1) {
        if (tid < s) red[tid] = fmaxf(red[tid], red[tid + s]);
        __syncthreads();
    }
    m = red[0];
    __syncthreads();
    float sum = 0.0f;
    #pragma unroll
    for (int i = 0; i < 8; i++) { v[i] = expf(v[i] - m); sum += v[i]; }
    red[tid] = sum; __syncthreads();
    #pragma unroll
    for (int s = 128; s > 0; s >>= 1) {
        if (tid < s) red[tid] += red[tid + s];
        __syncthreads();
    }
    const float inv = 1.0f / red[0];
    #pragma unroll
    for (int i = 0; i < 8; i++) {
        int c = tid + i * 256;
        if (c < nproc) {
            float pr = v[i] * inv;
            __half h = __float2half_rn(pr);
            Ph[row * 2048 + c] = h;
            Pl[row * 2048 + c] = __float2half_rn(pr - __half2float(h));
        }
    }
}

// ============ launcher ============
extern "C" void kernel_launch(void* const* d_in, const int* in_sizes, int n_in,
                              void* d_out, int out_size)
{
    const float* H   = (const float*)d_in[0];
    const int*   pos = (const int*)  d_in[2];
    const float* Wq  = (const float*)d_in[3];
    const float* WVT = (const float*)d_in[4];
    const float* U   = (const float*)d_in[5];
    const float* Wv  = (const float*)d_in[6];
    const float* Wo  = (const float*)d_in[7];
    float* out = (float*)d_out;

    const int SMEM1 = 5 * 16384;
    const int SMEM2 = 4 * 24576;
    const int SMEM3 = 3 * 32768;
    cudaFuncSetAttribute((const void*)wgemm<0,2>, cudaFuncAttributeMaxDynamicSharedMemorySize, SMEM2);
    cudaFuncSetAttribute((const void*)wgemm<0,1>, cudaFuncAttributeMaxDynamicSharedMemorySize, SMEM1);
    cudaFuncSetAttribute((const void*)wgemm<1,3>, cudaFuncAttributeMaxDynamicSharedMemorySize, SMEM3);
    cudaFuncSetAttribute((const void*)wgemm<2,2>, cudaFuncAttributeMaxDynamicSharedMemorySize, SMEM2);
    cudaFuncSetAttribute((const void*)wgemm<3,2>, cudaFuncAttributeMaxDynamicSharedMemorySize, SMEM2);

    __half *Hh, *Hl, *Wq1, *WVT1, *Wv1, *U1, *Wo1;
    __half *Qh, *Ql, *Kh, *Kl, *klath, *klatl, *vT1, *Ph, *Pl, *scrh;
    float *Qf, *Kf, *vlatf, *Pf;
    cudaGetSymbolAddress((void**)&Hh, g_Hh);       cudaGetSymbolAddress((void**)&Hl, g_Hl);
    cudaGetSymbolAddress((void**)&Wq1, g_Wq1);
    cudaGetSymbolAddress((void**)&WVT1, g_WVT1);
    cudaGetSymbolAddress((void**)&Wv1, g_Wv1);
    cudaGetSymbolAddress((void**)&U1, g_U1);
    cudaGetSymbolAddress((void**)&Wo1, g_Wo1);
    cudaGetSymbolAddress((void**)&Qf, g_Qf);       cudaGetSymbolAddress((void**)&Kf, g_Kf);
    cudaGetSymbolAddress((void**)&Qh, g_Qh);       cudaGetSymbolAddress((void**)&Ql, g_Ql);
    cudaGetSymbolAddress((void**)&Kh, g_Kh);       cudaGetSymbolAddress((void**)&Kl, g_Kl);
    cudaGetSymbolAddress((void**)&klath, g_klath); cudaGetSymbolAddress((void**)&klatl, g_klatl);
    cudaGetSymbolAddress((void**)&vlatf, g_vlatf);
    cudaGetSymbolAddress((void**)&vT1, g_vT1);
    cudaGetSymbolAddress((void**)&Pf, g_Pf);
    cudaGetSymbolAddress((void**)&Ph, g_Ph);       cudaGetSymbolAddress((void**)&Pl, g_Pl);
    cudaGetSymbolAddress((void**)&scrh, g_scrh);

    // our launch 0: ALL converts in one kernel
    convert_all<<<8192, 256>>>(H, Wq, WVT, Wv, U, Wo, Hh, Hl, Wq1, WVT1, Wv1, U1, Wo1);

    // our launch 1: klat = H @ WVT^T (4096x2048) -> fp16 hi/lo
    wgemm<3,2><<<dim3(16, 32, 1), 256, SMEM2>>>(
        Hh, Hl, WVT1, nullptr, klath, klatl, HID_, HID_, HID_, 2048,
        0, 0, 0, 0, 0, 0, 1, 1.0f);
    // our launch 2: vlat = H @ Wv^T (4096x2048) -> fp32
    wgemm<0,2><<<dim3(16, 32, 1), 256, SMEM2>>>(
        Hh, Hl, Wv1, nullptr, vlatf, nullptr, HID_, HID_, HID_, 2048,
        0, 0, 0, 0, 0, 0, 1, 1.0f);
    // our launch 3: Q = H @ Wq^T (4096x4096, K=4096) -> fp32   [ncu target if prepend=2]
    wgemm<0,2><<<dim3(32, 32, 1), 256, SMEM2>>>(
        Hh, Hl, Wq1, nullptr, Qf, nullptr, HID_, HID_, HID_, HID_,
        0, 0, 0, 0, 0, 0, 1, 1.0f);
    // our launch 4: K recon per (b,g): (2048x512, K=256) -> fp32  [ncu target if prepend=1]
    wgemm<0,2><<<dim3(4, 16, 16), 256, SMEM2>>>(
        klath, klatl, U1, nullptr, Kf, nullptr, RK_, 2048, 2048, HID_,
        (ll)S_ * 2048, RK_, 0, RK_, (ll)S_ * HID_, 512, G_, 1.0f);
    // our launch 5: vT transpose
    transpose_single<<<dim3(64, 64, B_), dim3(32, 8)>>>(vlatf, vT1);
    // our launch 6: RoPE -> hi/lo fp16 Q, K
    rope_split<<<B_ * S_, 256>>>(Qf, Kf, pos, Qh, Ql, Kh, Kl);
    // our launch 7: scores per (b,h): (2048x2048, K=128), 3-term, scale+causal -> fp32
    wgemm<1,3><<<dim3(16, 16, 64), 256, SMEM3>>>(
        Qh, Ql, Kh, Kl, Pf, nullptr, 128, HID_, HID_, S_,
        (ll)S_ * HID_, 128, (ll)S_ * HID_, 128,
        (ll)NH_ * S_ * S_, (ll)S_ * S_, NH_, 0.08838834764831845f);
    // our launch 8: softmax -> fp16 hi/lo probs (causal prefix only)
    softmax_split<<<B_ * NH_ * S_, 256>>>(Pf, Ph, Pl);
    // our launch 9: AV per (b,g): (8192x256, K truncated) -> scrambled fp16 (hi only)
    wgemm<2,2><<<dim3(2, 64, 16), 256, SMEM2>>>(
        Ph, Pl, vT1, nullptr, scrh, nullptr, S_, S_, S_, 0,
        (ll)NH_ * S_ * S_, (ll)4 * S_ * S_,
        (ll)2048 * 2048, (ll)FGD_ * S_,
        (ll)S_ * FH_, FGD_, G_, 1.0f);
    // our launch 10: out = scr @ Wo^T (4096x4096, K=8192), A single fp16
    wgemm<0,1><<<dim3(32, 32, 1), 256, SMEM1>>>(
        scrh, nullptr, Wo1, nullptr, out, nullptr, FH_, FH_, FH_, HID_,
        0, 0, 0, 0, 0, 0, 1, 1.0f);
}

// round 13
// speedup vs baseline: 1.2405x; 1.0529x over previous
#include <cuda_runtime.h>
#include <cuda_fp16.h>
#include <stdint.h>
#include <math.h>

typedef long long ll;
typedef unsigned int u32;
typedef unsigned long long u64;

static constexpr int B_   = 2;
static constexpr int S_   = 2048;
static constexpr int HID_ = 4096;
static constexpr int NH_  = 32;
static constexpr int G_   = 8;
static constexpr int RK_  = 256;
static constexpr int FGD_ = 256;
static constexpr int FH_  = 8192;

static constexpr ll N_H   = (ll)B_ * S_ * HID_;
static constexpr ll N_WQ  = (ll)HID_ * HID_;
static constexpr ll N_WVT = (ll)(G_*RK_) * HID_;
static constexpr ll N_WV  = (ll)(G_*FGD_) * HID_;
static constexpr ll N_U   = (ll)512 * (G_*RK_);
static constexpr ll N_WO  = (ll)HID_ * FH_;
static constexpr ll N_LAT = (ll)B_ * S_ * (G_*RK_);
static constexpr ll N_P   = (ll)B_ * NH_ * S_ * S_;
static constexpr ll N_SCR = (ll)B_ * S_ * FH_;

__device__ __half g_Hh[N_H],     g_Hl[N_H];
__device__ __half g_Wq1[N_WQ];
__device__ __half g_WVT1[N_WVT];
__device__ __half g_Wv1[N_WV];
__device__ __half g_U1[N_U];
__device__ __half g_Wo1[N_WO];
__device__ float  g_Qf[N_H],    g_Kf[N_H];
__device__ __half g_Qh[N_H], g_Ql[N_H], g_Kh[N_H], g_Kl[N_H];
__device__ __half g_klath[N_LAT], g_klatl[N_LAT];
__device__ float  g_vlatf[N_LAT];
__device__ __half g_vT1[N_LAT];
__device__ float  g_Pf[N_P];
__device__ __half g_Ph[N_P];
__device__ __half g_scrh[N_SCR];

// ---------------- PTX helpers ----------------
__device__ __forceinline__ u32 smem_u32(const void* p) {
    u32 a;
    asm("{ .reg .u64 t; cvta.to.shared.u64 t, %1; cvt.u32.u64 %0, t; }" : "=r"(a) : "l"(p));
    return a;
}
__device__ __forceinline__ void cp16(u32 dst, const void* src) {
    asm volatile("cp.async.cg.shared.global [%0], [%1], 16;" :: "r"(dst), "l"(src));
}
__device__ __forceinline__ void cp_commit() { asm volatile("cp.async.commit_group;" ::: "memory"); }
template<int N>
__device__ __forceinline__ void cp_waitN() { asm volatile("cp.async.wait_group %0;" :: "n"(N) : "memory"); }
__device__ __forceinline__ void ldsm4(u32* r, u32 addr) {
    asm volatile("ldmatrix.sync.aligned.m8n8.x4.shared.b16 {%0,%1,%2,%3}, [%4];"
                 : "=r"(r[0]), "=r"(r[1]), "=r"(r[2]), "=r"(r[3]) : "r"(addr));
}
__device__ __forceinline__ void mma16816(float* d, const u32* a, const u32* b) {
    asm volatile("mma.sync.aligned.m16n8k16.row.col.f32.f16.f16.f32 "
                 "{%0,%1,%2,%3}, {%4,%5,%6,%7}, {%8,%9}, {%0,%1,%2,%3};"
                 : "+f"(d[0]), "+f"(d[1]), "+f"(d[2]), "+f"(d[3])
                 : "r"(a[0]), "r"(a[1]), "r"(a[2]), "r"(a[3]), "r"(b[0]), "r"(b[1]));
}
__device__ __forceinline__ u32 pack_hi(float v0, float v1) {
    __half2 p = __halves2half2(__float2half_rn(v0), __float2half_rn(v1));
    return *(u32*)&p;
}
__device__ __forceinline__ u32 pack_lo(float v0, float v1) {
    __half h0 = __float2half_rn(v0), h1 = __float2half_rn(v1);
    __half2 p = __halves2half2(__float2half_rn(v0 - __half2float(h0)),
                               __float2half_rn(v1 - __half2float(h1)));
    return *(u32*)&p;
}
// conflict-free 16B-slot swizzle for 64B rows: slot distinct over any 8-row window
__device__ __forceinline__ u32 swz(int r, int c) {
    return (u32)(r * 64 + (((c ^ ((r >> 1) & 3)) & 3) << 4));
}

// ======================================================================================
// warp-MMA fp16 GEMM, CTA tile 128x128, 8 warps (2x4), warp tile 64x32, 2 CTAs/SM.
//   PREC=1: A single fp16,  1 MMA/k-step, stage 16K, 5-deep
//   PREC=2: A hi/lo fp16,   2 MMAs/k-step, stage 24K, 4-deep
//   PREC=3: A hi/lo + B hi/lo, 3 MMAs/k-step, stage 32K, 3-deep (1 CTA/SM)
// MODE 0: f32 store  MODE 1: scores (scale+causal; skip masked tiles)
// MODE 2: AV (K truncation + PALU scramble; lo plane only if C1v!=null)
// MODE 3: fp16 plain store (hi, + lo if C1v)
// ======================================================================================
template<int MODE, int PREC>
__global__ void __launch_bounds__(256, PREC == 3 ? 1 : 2)
wgemm(const __half* __restrict__ Ah, const __half* __restrict__ Al,
      const __half* __restrict__ Bh, const __half* __restrict__ Bl,
      void* C0v, void* C1v, int K, int lda, int ldb, int ldc,
      ll aSo, ll aSi, ll bSo, ll bSi, ll cSo, ll cSi, int ziCount, float scale)
{
    constexpr int STAGE  = (PREC == 3) ? 32768 : (PREC == 2 ? 24576 : 16384);
    constexpr int NSTAGE = (PREC == 3) ? 3 : (PREC == 2 ? 4 : 5);
    constexpr int BOFF   = (PREC >= 2) ? 16384 : 8192;
    const int row0 = blockIdx.y * 128;
    const int col0 = blockIdx.x * 128;
    if (MODE == 1 && col0 > row0 + 127) return;

    const int zo = blockIdx.z / ziCount, zi = blockIdx.z % ziCount;
    const ll aOff = (ll)zo * aSo + (ll)zi * aSi + (ll)row0 * lda;
    const ll bOff = (ll)zo * bSo + (ll)zi * bSi + (ll)col0 * ldb;
    Ah += aOff; Bh += bOff;
    if (PREC >= 2) Al += aOff;
    if (PREC == 3) Bl += bOff;
    const ll cOff = (ll)zo * cSo + (ll)zi * cSi;

    int Keff = K;
    if (MODE == 2) { int lim = (row0 & 2047) + 128; if (lim < Keff) Keff = lim; }
    const int nK = Keff >> 5;

    extern __shared__ char sm[];
    const u32 sb = smem_u32(sm);
    const int tid = threadIdx.x, wid = tid >> 5, lane = tid & 31;
    const int wm = wid >> 2, wn = wid & 3;

    float acc[4][4][4];
    #pragma unroll
    for (int a = 0; a < 4; a++)
        #pragma unroll
        for (int b = 0; b < 4; b++)
            #pragma unroll
            for (int c = 0; c < 4; c++) acc[a][b][c] = 0.0f;

    auto load_stage = [&](int kt) {
        const u32 sbase = sb + (kt % NSTAGE) * STAGE;
        const int k0 = kt << 5;
        constexpr int NCHUNK = (PREC == 3) ? 8 : (PREC == 2 ? 6 : 4);
        constexpr int NA = (PREC >= 2) ? 1024 : 512;
        #pragma unroll
        for (int i = 0; i < NCHUNK; i++) {
            int idx = tid + i * 256;
            if (idx < NA) {                        // A: hi (and lo if PREC>=2)
                int sub = (PREC >= 2) ? (idx >> 9) : 0;
                int m = (PREC >= 2) ? (idx & 511) : idx;
                int r = m >> 2, c = m & 3;
                u32 d = sbase + sub * 8192 + swz(r, c);
                const __half* src = sub ? Al : Ah;
                cp16(d, src + (ll)r * lda + k0 + c * 8);
            } else {                               // B: 128 rows
                int j = idx - NA;
                int sub = (PREC == 3) ? (j >> 9) : 0;
                int m = (PREC == 3) ? (j & 511) : j;
                int r = m >> 2, c = m & 3;
                u32 d = sbase + BOFF + sub * 8192 + swz(r, c);
                const __half* src = (PREC == 3 && sub) ? Bl : Bh;
                cp16(d, src + (ll)r * ldb + k0 + c * 8);
            }
        }
    };

    #pragma unroll
    for (int s = 0; s < NSTAGE - 1; s++) {
        if (s == 0 || s < nK) load_stage(s);
        cp_commit();
    }

    for (int kt = 0; kt < nK; kt++) {
        if (kt + NSTAGE - 1 < nK) load_stage(kt + NSTAGE - 1);
        cp_commit();
        cp_waitN<NSTAGE - 1>();
        __syncthreads();

        const u32 abase = sb + (kt % NSTAGE) * STAGE;
        #pragma unroll
        for (int kk = 0; kk < 2; kk++) {
            u32 aH[4][4], aL[4][4];
            #pragma unroll
            for (int mi = 0; mi < 4; mi++) {
                int row = wm * 64 + mi * 16 + ((lane >> 3) & 1) * 8 + (lane & 7);
                int kb4 = kk * 2 + ((lane >> 4) & 1);
                u32 ad = abase + swz(row, kb4);
                ldsm4(aH[mi], ad);
                if (PREC >= 2) ldsm4(aL[mi], ad + 8192);
            }
            #pragma unroll
            for (int nj = 0; nj < 2; nj++) {
                int n = wn * 32 + nj * 16 + ((lane >> 4) & 1) * 8 + (lane & 7);
                int kb4 = kk * 2 + ((lane >> 3) & 1);
                u32 bd = abase + BOFF + swz(n, kb4);
                u32 tH[4];
                ldsm4(tH, bd);
                if (PREC == 3) {
                    u32 tL[4];
                    ldsm4(tL, bd + 8192);
                    #pragma unroll
                    for (int mi = 0; mi < 4; mi++) {
                        mma16816(acc[mi][nj*2],   aH[mi], tH);
                        mma16816(acc[mi][nj*2],   aH[mi], tL);
                        mma16816(acc[mi][nj*2],   aL[mi], tH);
                        mma16816(acc[mi][nj*2+1], aH[mi], tH + 2);
                        mma16816(acc[mi][nj*2+1], aH[mi], tL + 2);
                        mma16816(acc[mi][nj*2+1], aL[mi], tH + 2);
                    }
                } else if (PREC == 2) {
                    #pragma unroll
                    for (int mi = 0; mi < 4; mi++) {
                        mma16816(acc[mi][nj*2],   aH[mi], tH);
                        mma16816(acc[mi][nj*2],   aL[mi], tH);
                        mma16816(acc[mi][nj*2+1], aH[mi], tH + 2);
                        mma16816(acc[mi][nj*2+1], aL[mi], tH + 2);
                    }
                } else {
                    #pragma unroll
                    for (int mi = 0; mi < 4; mi++) {
                        mma16816(acc[mi][nj*2],   aH[mi], tH);
                        mma16816(acc[mi][nj*2+1], aH[mi], tH + 2);
                    }
                }
            }
        }
        __syncthreads();
    }

    // ---- epilogue ----
    const int g = lane >> 2, tig = lane & 3;
    #pragma unroll
    for (int mi = 0; mi < 4; mi++) {
        #pragma unroll
        for (int ni = 0; ni < 4; ni++) {
            int r1 = row0 + wm * 64 + mi * 16 + g;
            int r2 = r1 + 8;
            int col = col0 + wn * 32 + ni * 8 + tig * 2;
            float* ac = acc[mi][ni];
            if (MODE == 0) {
                float* C = (float*)C0v + cOff;
                *(float2*)(C + (ll)r1 * ldc + col) = make_float2(ac[0], ac[1]);
                *(float2*)(C + (ll)r2 * ldc + col) = make_float2(ac[2], ac[3]);
            } else if (MODE == 1) {
                float* C = (float*)C0v + cOff;
                float2 v1, v2;
                v1.x = (col     > r1) ? -1e30f : ac[0] * scale;
                v1.y = (col + 1 > r1) ? -1e30f : ac[1] * scale;
                v2.x = (col     > r2) ? -1e30f : ac[2] * scale;
                v2.y = (col + 1 > r2) ? -1e30f : ac[3] * scale;
                *(float2*)(C + (ll)r1 * ldc + col) = v1;
                *(float2*)(C + (ll)r2 * ldc + col) = v2;
            } else {
                __half* Ch = (__half*)C0v;
                __half* Cl = (__half*)C1v;
                ll b1, b2;
                if (MODE == 3) {
                    b1 = cOff + (ll)r1 * ldc + col;
                    b2 = cOff + (ll)r2 * ldc + col;
                } else {
                    int hg1 = r1 >> 11, s1 = r1 & 2047;
                    int hg2 = r2 >> 11, s2 = r2 & 2047;
                    b1 = cOff + (ll)(hg1 * 512 + (s1 >> 2)) * FH_ + (ll)(s1 & 3) * 2048 + col;
                    b2 = cOff + (ll)(hg2 * 512 + (s2 >> 2)) * FH_ + (ll)(s2 & 3) * 2048 + col;
                }
                *(u32*)(Ch + b1) = pack_hi(ac[0], ac[1]);
                *(u32*)(Ch + b2) = pack_hi(ac[2], ac[3]);
                if (Cl) {
                    *(u32*)(Cl + b1) = pack_lo(ac[0], ac[1]);
                    *(u32*)(Cl + b2) = pack_lo(ac[2], ac[3]);
                }
            }
        }
    }
}

// ============ mega-convert: all fp32 -> fp16 conversions in ONE launch ============
static constexpr ll C_H   = N_H   / 4;
static constexpr ll C_WQ  = C_H   + N_WQ  / 4;
static constexpr ll C_WVT = C_WQ  + N_WVT / 4;
static constexpr ll C_WV  = C_WVT + N_WV  / 4;
static constexpr ll C_U   = C_WV  + N_U   / 4;
static constexpr ll C_WO  = C_U   + N_WO  / 4;

__global__ void convert_all(const float* __restrict__ H,  const float* __restrict__ Wq,
                            const float* __restrict__ WVT, const float* __restrict__ Wv,
                            const float* __restrict__ U,  const float* __restrict__ Wo,
                            __half* __restrict__ Hh, __half* __restrict__ Hl,
                            __half* __restrict__ Wq1, __half* __restrict__ WVT1,
                            __half* __restrict__ Wv1, __half* __restrict__ U1,
                            __half* __restrict__ Wo1)
{
    ll i = (ll)blockIdx.x * blockDim.x + threadIdx.x;
    const ll stride = (ll)gridDim.x * blockDim.x;
    for (; i < C_WO; i += stride) {
        const float* src; __half* dh; __half* dl = nullptr; ll j;
        if (i < C_H)        { src = H;   dh = Hh;   dl = Hl; j = i; }
        else if (i < C_WQ)  { src = Wq;  dh = Wq1;  j = i - C_H; }
        else if (i < C_WVT) { src = WVT; dh = WVT1; j = i - C_WQ; }
        else if (i < C_WV)  { src = Wv;  dh = Wv1;  j = i - C_WVT; }
        else if (i < C_U)   { src = U;   dh = U1;   j = i - C_WV; }
        else                { src = Wo;  dh = Wo1;  j = i - C_U; }
        float4 v = __ldg((const float4*)src + j);
        ((uint2*)dh)[j] = make_uint2(pack_hi(v.x, v.y), pack_hi(v.z, v.w));
        if (dl) ((uint2*)dl)[j] = make_uint2(pack_lo(v.x, v.y), pack_lo(v.z, v.w));
    }
}

// ============ RoPE: fp32 Q/K -> rotated (hi,lo) fp16 ============
__global__ void rope_split(const float* __restrict__ Qf, const float* __restrict__ Kf,
                           const int* __restrict__ pos,
                           __half* __restrict__ Qh, __half* __restrict__ Ql,
                           __half* __restrict__ Kh, __half* __restrict__ Kl)
{
    const int row = blockIdx.x;
    const float p = (float)__ldg(pos + row);
    const ll base = (ll)row * HID_;
    for (int t = threadIdx.x; t < NH_ * 64; t += blockDim.x) {
        int h = t >> 6, d = t & 63;
        float inv = exp2f(-(float)d * (13.287712379549449f / 64.0f));
        float sn, cs;
        sincosf(p * inv, &sn, &cs);
        ll c1 = base + h * 128 + d, c2 = c1 + 64;
        float qx = Qf[c1], qy = Qf[c2];
        float q1 = qx * cs - qy * sn, q2 = qy * cs + qx * sn;
        __half a = __float2half_rn(q1); Qh[c1] = a; Ql[c1] = __float2half_rn(q1 - __half2float(a));
        __half b = __float2half_rn(q2); Qh[c2] = b; Ql[c2] = __float2half_rn(q2 - __half2float(b));
        float kx = Kf[c1], ky = Kf[c2];
        float k1 = kx * cs - ky * sn, k2 = ky * cs + kx * sn;
        __half c = __float2half_rn(k1); Kh[c1] = c; Kl[c1] = __float2half_rn(k1 - __half2float(c));
        __half e = __float2half_rn(k2); Kh[c2] = e; Kl[c2] = __float2half_rn(k2 - __half2float(e));
    }
}

// ============ transpose: vlat[b*2048+s][2048] -> vT[b*2048+n][s] single fp16 ============
__global__ void transpose_single(const float* __restrict__ V, __half* __restrict__ Th)
{
    __shared__ float t[32][33];
    const int b = blockIdx.z, s0 = blockIdx.x * 32, n0 = blockIdx.y * 32;
    const int x = threadIdx.x;
    for (int y = threadIdx.y; y < 32; y += 8)
        t[y][x] = __ldg(V + (ll)(b * 2048 + s0 + y) * 2048 + n0 + x);
    __syncthreads();
    for (int yo = threadIdx.y; yo < 32; yo += 8) {
        ll idx = (ll)(b * 2048 + n0 + yo) * 2048 + s0 + x;
        Th[idx] = __float2half_rn(t[x][yo]);
    }
}

// ============ causal-prefix softmax: fp32 logits -> single fp16 probs ============
__global__ void __launch_bounds__(256) softmax_single(const float* __restrict__ Pf,
                                                      __half* __restrict__ Ph)
{
    const ll row = blockIdx.x;
    const int rl = (int)(row & 2047);
    const int nproc = ((rl >> 7) + 1) << 7;
    const float* src = Pf + row * 2048;
    const int tid = threadIdx.x;
    float v[8];
    float m = -1e38f;
    #pragma unroll
    for (int i = 0; i < 8; i++) {
        int c = tid + i * 256;
        v[i] = (c < nproc) ? src[c] : -1e38f;
        m = fmaxf(m, v[i]);
    }
    __shared__ float red[256];
    red[tid] = m; __syncthreads();
    #pragma unroll
    for (int s = 128; s > 0; s >>= 1) {
        if (tid < s) red[tid] = fmaxf(red[tid], red[tid + s]);
        __syncthreads();
    }
    m = red[0];
    __syncthreads();
    float sum = 0.0f;
    #pragma unroll
    for (int i = 0; i < 8; i++) { v[i] = expf(v[i] - m); sum += v[i]; }
    red[tid] = sum; __syncthreads();
    #pragma unroll
    for (int s = 128; s > 0; s >>= 1) {
        if (tid < s) red[tid] += red[tid + s];
        __syncthreads();
    }
    const float inv = 1.0f / red[0];
    #pragma unroll
    for (int i = 0; i < 8; i++) {
        int c = tid + i * 256;
        if (c < nproc)
            Ph[row * 2048 + c] = __float2half_rn(v[i] * inv);
    }
}

// ============ launcher ============
extern "C" void kernel_launch(void* const* d_in, const int* in_sizes, int n_in,
                              void* d_out, int out_size)
{
    const float* H   = (const float*)d_in[0];
    const int*   pos = (const int*)  d_in[2];
    const float* Wq  = (const float*)d_in[3];
    const float* WVT = (const float*)d_in[4];
    const float* U   = (const float*)d_in[5];
    const float* Wv  = (const float*)d_in[6];
    const float* Wo  = (const float*)d_in[7];
    float* out = (float*)d_out;

    const int SMEM1 = 5 * 16384;
    const int SMEM2 = 4 * 24576;
    const int SMEM3 = 3 * 32768;
    cudaFuncSetAttribute((const void*)wgemm<0,2>, cudaFuncAttributeMaxDynamicSharedMemorySize, SMEM2);
    cudaFuncSetAttribute((const void*)wgemm<0,1>, cudaFuncAttributeMaxDynamicSharedMemorySize, SMEM1);
    cudaFuncSetAttribute((const void*)wgemm<1,3>, cudaFuncAttributeMaxDynamicSharedMemorySize, SMEM3);
    cudaFuncSetAttribute((const void*)wgemm<2,1>, cudaFuncAttributeMaxDynamicSharedMemorySize, SMEM1);
    cudaFuncSetAttribute((const void*)wgemm<3,2>, cudaFuncAttributeMaxDynamicSharedMemorySize, SMEM2);

    __half *Hh, *Hl, *Wq1, *WVT1, *Wv1, *U1, *Wo1;
    __half *Qh, *Ql, *Kh, *Kl, *klath, *klatl, *vT1, *Ph, *scrh;
    float *Qf, *Kf, *vlatf, *Pf;
    cudaGetSymbolAddress((void**)&Hh, g_Hh);       cudaGetSymbolAddress((void**)&Hl, g_Hl);
    cudaGetSymbolAddress((void**)&Wq1, g_Wq1);
    cudaGetSymbolAddress((void**)&WVT1, g_WVT1);
    cudaGetSymbolAddress((void**)&Wv1, g_Wv1);
    cudaGetSymbolAddress((void**)&U1, g_U1);
    cudaGetSymbolAddress((void**)&Wo1, g_Wo1);
    cudaGetSymbolAddress((void**)&Qf, g_Qf);       cudaGetSymbolAddress((void**)&Kf, g_Kf);
    cudaGetSymbolAddress((void**)&Qh, g_Qh);       cudaGetSymbolAddress((void**)&Ql, g_Ql);
    cudaGetSymbolAddress((void**)&Kh, g_Kh);       cudaGetSymbolAddress((void**)&Kl, g_Kl);
    cudaGetSymbolAddress((void**)&klath, g_klath); cudaGetSymbolAddress((void**)&klatl, g_klatl);
    cudaGetSymbolAddress((void**)&vlatf, g_vlatf);
    cudaGetSymbolAddress((void**)&vT1, g_vT1);
    cudaGetSymbolAddress((void**)&Pf, g_Pf);
    cudaGetSymbolAddress((void**)&Ph, g_Ph);
    cudaGetSymbolAddress((void**)&scrh, g_scrh);

    // our launch 0: ALL converts in one kernel
    convert_all<<<8192, 256>>>(H, Wq, WVT, Wv, U, Wo, Hh, Hl, Wq1, WVT1, Wv1, U1, Wo1);

    // our launch 1: klat = H @ WVT^T (4096x2048) -> fp16 hi/lo
    wgemm<3,2><<<dim3(16, 32, 1), 256, SMEM2>>>(
        Hh, Hl, WVT1, nullptr, klath, klatl, HID_, HID_, HID_, 2048,
        0, 0, 0, 0, 0, 0, 1, 1.0f);
    // our launch 2: vlat = H @ Wv^T (4096x2048) -> fp32
    wgemm<0,2><<<dim3(16, 32, 1), 256, SMEM2>>>(
        Hh, Hl, Wv1, nullptr, vlatf, nullptr, HID_, HID_, HID_, 2048,
        0, 0, 0, 0, 0, 0, 1, 1.0f);
    // our launch 3: Q = H @ Wq^T (4096x4096, K=4096) -> fp32
    wgemm<0,2><<<dim3(32, 32, 1), 256, SMEM2>>>(
        Hh, Hl, Wq1, nullptr, Qf, nullptr, HID_, HID_, HID_, HID_,
        0, 0, 0, 0, 0, 0, 1, 1.0f);
    // our launch 4: K recon per (b,g): (2048x512, K=256) -> fp32
    wgemm<0,2><<<dim3(4, 16, 16), 256, SMEM2>>>(
        klath, klatl, U1, nullptr, Kf, nullptr, RK_, 2048, 2048, HID_,
        (ll)S_ * 2048, RK_, 0, RK_, (ll)S_ * HID_, 512, G_, 1.0f);
    // our launch 5: vT transpose
    transpose_single<<<dim3(64, 64, B_), dim3(32, 8)>>>(vlatf, vT1);
    // our launch 6: RoPE -> hi/lo fp16 Q, K
    rope_split<<<B_ * S_, 256>>>(Qf, Kf, pos, Qh, Ql, Kh, Kl);
    // our launch 7: scores per (b,h): (2048x2048, K=128), 3-term, scale+causal -> fp32
    wgemm<1,3><<<dim3(16, 16, 64), 256, SMEM3>>>(
        Qh, Ql, Kh, Kl, Pf, nullptr, 128, HID_, HID_, S_,
        (ll)S_ * HID_, 128, (ll)S_ * HID_, 128,
        (ll)NH_ * S_ * S_, (ll)S_ * S_, NH_, 0.08838834764831845f);
    // our launch 8: softmax -> single fp16 probs (causal prefix only)
    softmax_single<<<B_ * NH_ * S_, 256>>>(Pf, Ph);
    // our launch 9: AV per (b,g): (8192x256, K truncated), P single fp16 -> scrambled fp16
    wgemm<2,1><<<dim3(2, 64, 16), 256, SMEM1>>>(
        Ph, nullptr, vT1, nullptr, scrh, nullptr, S_, S_, S_, 0,
        (ll)NH_ * S_ * S_, (ll)4 * S_ * S_,
        (ll)2048 * 2048, (ll)FGD_ * S_,
        (ll)S_ * FH_, FGD_, G_, 1.0f);
    // our launch 10: out = scr @ Wo^T (4096x4096, K=8192), A single fp16
    wgemm<0,1><<<dim3(32, 32, 1), 256, SMEM1>>>(
        scrh, nullptr, Wo1, nullptr, out, nullptr, FH_, FH_, FH_, HID_,
        0, 0, 0, 0, 0, 0, 1, 1.0f);
}

// round 14
// speedup vs baseline: 1.3375x; 1.0782x over previous
#include <cuda_runtime.h>
#include <cuda_fp16.h>
#include <stdint.h>
#include <math.h>

typedef long long ll;
typedef unsigned int u32;
typedef unsigned long long u64;

static constexpr int B_   = 2;
static constexpr int S_   = 2048;
static constexpr int HID_ = 4096;
static constexpr int NH_  = 32;
static constexpr int G_   = 8;
static constexpr int RK_  = 256;
static constexpr int FGD_ = 256;
static constexpr int FH_  = 8192;

static constexpr ll N_H   = (ll)B_ * S_ * HID_;
static constexpr ll N_WQ  = (ll)HID_ * HID_;
static constexpr ll N_WVT = (ll)(G_*RK_) * HID_;
static constexpr ll N_WV  = (ll)(G_*FGD_) * HID_;
static constexpr ll N_U   = (ll)512 * (G_*RK_);
static constexpr ll N_WO  = (ll)HID_ * FH_;
static constexpr ll N_LAT = (ll)B_ * S_ * (G_*RK_);
static constexpr ll N_P   = (ll)B_ * NH_ * S_ * S_;
static constexpr ll N_SCR = (ll)B_ * S_ * FH_;

__device__ __half g_Hh[N_H],     g_Hl[N_H];
__device__ __half g_Wq1[N_WQ];
__device__ __half g_WVT1[N_WVT];
__device__ __half g_Wv1[N_WV];
__device__ __half g_U1[N_U];
__device__ __half g_Wo1[N_WO];
__device__ float  g_Qf[N_H],    g_Kf[N_H];
__device__ __half g_Qh[N_H], g_Ql[N_H], g_Kh[N_H], g_Kl[N_H];
__device__ __half g_klath[N_LAT], g_klatl[N_LAT];
__device__ float  g_vlatf[N_LAT];
__device__ __half g_vT1[N_LAT];
__device__ float  g_Pf[N_P];
__device__ __half g_Ph[N_P];
__device__ __half g_scrh[N_SCR];

// ---------------- PTX helpers ----------------
__device__ __forceinline__ u32 smem_u32(const void* p) {
    u32 a;
    asm("{ .reg .u64 t; cvta.to.shared.u64 t, %1; cvt.u32.u64 %0, t; }" : "=r"(a) : "l"(p));
    return a;
}
__device__ __forceinline__ void cp16(u32 dst, const void* src) {
    asm volatile("cp.async.cg.shared.global [%0], [%1], 16;" :: "r"(dst), "l"(src));
}
__device__ __forceinline__ void cp_commit() { asm volatile("cp.async.commit_group;" ::: "memory"); }
template<int N>
__device__ __forceinline__ void cp_waitN() { asm volatile("cp.async.wait_group %0;" :: "n"(N) : "memory"); }
__device__ __forceinline__ void ldsm4(u32* r, u32 addr) {
    asm volatile("ldmatrix.sync.aligned.m8n8.x4.shared.b16 {%0,%1,%2,%3}, [%4];"
                 : "=r"(r[0]), "=r"(r[1]), "=r"(r[2]), "=r"(r[3]) : "r"(addr));
}
__device__ __forceinline__ void mma16816(float* d, const u32* a, const u32* b) {
    asm volatile("mma.sync.aligned.m16n8k16.row.col.f32.f16.f16.f32 "
                 "{%0,%1,%2,%3}, {%4,%5,%6,%7}, {%8,%9}, {%0,%1,%2,%3};"
                 : "+f"(d[0]), "+f"(d[1]), "+f"(d[2]), "+f"(d[3])
                 : "r"(a[0]), "r"(a[1]), "r"(a[2]), "r"(a[3]), "r"(b[0]), "r"(b[1]));
}
__device__ __forceinline__ u32 pack_hi(float v0, float v1) {
    __half2 p = __halves2half2(__float2half_rn(v0), __float2half_rn(v1));
    return *(u32*)&p;
}
__device__ __forceinline__ u32 pack_lo(float v0, float v1) {
    __half h0 = __float2half_rn(v0), h1 = __float2half_rn(v1);
    __half2 p = __halves2half2(__float2half_rn(v0 - __half2float(h0)),
                               __float2half_rn(v1 - __half2float(h1)));
    return *(u32*)&p;
}
// conflict-free 16B-slot swizzle for 64B rows
__device__ __forceinline__ u32 swz(int r, int c) {
    return (u32)(r * 64 + (((c ^ ((r >> 1) & 3)) & 3) << 4));
}

// ======================================================================================
// warp-MMA fp16 GEMM, CTA tile 128x128, 8 warps (2x4), warp tile 64x32, 2 CTAs/SM.
// Single-barrier multistage mainloop: wait -> sync -> issue next loads -> commit -> MMA.
//   PREC=1: A single fp16,  1 MMA/k-step, stage 16K, 5-deep
//   PREC=2: A hi/lo fp16,   2 MMAs/k-step, stage 24K, 4-deep
//   PREC=3: A hi/lo + B hi/lo, 3 MMAs/k-step, stage 32K, 3-deep
// MODE 0: f32 store  MODE 1: scores (scale+causal; skip masked tiles)
// MODE 2: AV (K truncation + PALU scramble; lo plane only if C1v!=null)
// MODE 3: fp16 plain store (hi, + lo if C1v)
// ======================================================================================
template<int MODE, int PREC>
__global__ void __launch_bounds__(256, 2)
wgemm(const __half* __restrict__ Ah, const __half* __restrict__ Al,
      const __half* __restrict__ Bh, const __half* __restrict__ Bl,
      void* C0v, void* C1v, int K, int lda, int ldb, int ldc,
      ll aSo, ll aSi, ll bSo, ll bSi, ll cSo, ll cSi, int ziCount, float scale)
{
    constexpr int STAGE  = (PREC == 3) ? 32768 : (PREC == 2 ? 24576 : 16384);
    constexpr int NSTAGE = (PREC == 3) ? 3 : (PREC == 2 ? 4 : 5);
    constexpr int BOFF   = (PREC >= 2) ? 16384 : 8192;
    const int row0 = blockIdx.y * 128;
    const int col0 = blockIdx.x * 128;
    if (MODE == 1 && col0 > row0 + 127) return;

    const int zo = blockIdx.z / ziCount, zi = blockIdx.z % ziCount;
    const ll aOff = (ll)zo * aSo + (ll)zi * aSi + (ll)row0 * lda;
    const ll bOff = (ll)zo * bSo + (ll)zi * bSi + (ll)col0 * ldb;
    Ah += aOff; Bh += bOff;
    if (PREC >= 2) Al += aOff;
    if (PREC == 3) Bl += bOff;
    const ll cOff = (ll)zo * cSo + (ll)zi * cSi;

    int Keff = K;
    if (MODE == 2) { int lim = (row0 & 2047) + 128; if (lim < Keff) Keff = lim; }
    const int nK = Keff >> 5;

    extern __shared__ char sm[];
    const u32 sb = smem_u32(sm);
    const int tid = threadIdx.x, wid = tid >> 5, lane = tid & 31;
    const int wm = wid >> 2, wn = wid & 3;

    float acc[4][4][4];
    #pragma unroll
    for (int a = 0; a < 4; a++)
        #pragma unroll
        for (int b = 0; b < 4; b++)
            #pragma unroll
            for (int c = 0; c < 4; c++) acc[a][b][c] = 0.0f;

    auto load_stage = [&](int kt) {
        const u32 sbase = sb + (kt % NSTAGE) * STAGE;
        const int k0 = kt << 5;
        constexpr int NCHUNK = (PREC == 3) ? 8 : (PREC == 2 ? 6 : 4);
        constexpr int NA = (PREC >= 2) ? 1024 : 512;
        #pragma unroll
        for (int i = 0; i < NCHUNK; i++) {
            int idx = tid + i * 256;
            if (idx < NA) {
                int sub = (PREC >= 2) ? (idx >> 9) : 0;
                int m = (PREC >= 2) ? (idx & 511) : idx;
                int r = m >> 2, c = m & 3;
                u32 d = sbase + sub * 8192 + swz(r, c);
                const __half* src = sub ? Al : Ah;
                cp16(d, src + (ll)r * lda + k0 + c * 8);
            } else {
                int j = idx - NA;
                int sub = (PREC == 3) ? (j >> 9) : 0;
                int m = (PREC == 3) ? (j & 511) : j;
                int r = m >> 2, c = m & 3;
                u32 d = sbase + BOFF + sub * 8192 + swz(r, c);
                const __half* src = (PREC == 3 && sub) ? Bl : Bh;
                cp16(d, src + (ll)r * ldb + k0 + c * 8);
            }
        }
    };

    // prologue: NSTAGE-1 committed groups
    #pragma unroll
    for (int s = 0; s < NSTAGE - 1; s++) {
        if (s == 0 || s < nK) load_stage(s);
        cp_commit();
    }

    for (int kt = 0; kt < nK; kt++) {
        cp_waitN<NSTAGE - 2>();     // stage kt resident
        __syncthreads();            // all reads of buffer (kt-1) finished before this
        if (kt + NSTAGE - 1 < nK) load_stage(kt + NSTAGE - 1);   // writes buffer (kt-1)%NSTAGE
        cp_commit();

        const u32 abase = sb + (kt % NSTAGE) * STAGE;
        #pragma unroll
        for (int kk = 0; kk < 2; kk++) {
            u32 aH[4][4], aL[4][4];
            #pragma unroll
            for (int mi = 0; mi < 4; mi++) {
                int row = wm * 64 + mi * 16 + ((lane >> 3) & 1) * 8 + (lane & 7);
                int kb4 = kk * 2 + ((lane >> 4) & 1);
                u32 ad = abase + swz(row, kb4);
                ldsm4(aH[mi], ad);
                if (PREC >= 2) ldsm4(aL[mi], ad + 8192);
            }
            #pragma unroll
            for (int nj = 0; nj < 2; nj++) {
                int n = wn * 32 + nj * 16 + ((lane >> 4) & 1) * 8 + (lane & 7);
                int kb4 = kk * 2 + ((lane >> 3) & 1);
                u32 bd = abase + BOFF + swz(n, kb4);
                u32 tH[4];
                ldsm4(tH, bd);
                if (PREC == 3) {
                    u32 tL[4];
                    ldsm4(tL, bd + 8192);
                    #pragma unroll
                    for (int mi = 0; mi < 4; mi++) {
                        mma16816(acc[mi][nj*2],   aH[mi], tH);
                        mma16816(acc[mi][nj*2],   aH[mi], tL);
                        mma16816(acc[mi][nj*2],   aL[mi], tH);
                        mma16816(acc[mi][nj*2+1], aH[mi], tH + 2);
                        mma16816(acc[mi][nj*2+1], aH[mi], tL + 2);
                        mma16816(acc[mi][nj*2+1], aL[mi], tH + 2);
                    }
                } else if (PREC == 2) {
                    #pragma unroll
                    for (int mi = 0; mi < 4; mi++) {
                        mma16816(acc[mi][nj*2],   aH[mi], tH);
                        mma16816(acc[mi][nj*2],   aL[mi], tH);
                        mma16816(acc[mi][nj*2+1], aH[mi], tH + 2);
                        mma16816(acc[mi][nj*2+1], aL[mi], tH + 2);
                    }
                } else {
                    #pragma unroll
                    for (int mi = 0; mi < 4; mi++) {
                        mma16816(acc[mi][nj*2],   aH[mi], tH);
                        mma16816(acc[mi][nj*2+1], aH[mi], tH + 2);
                    }
                }
            }
        }
    }

    // ---- epilogue ----
    const int g = lane >> 2, tig = lane & 3;
    #pragma unroll
    for (int mi = 0; mi < 4; mi++) {
        #pragma unroll
        for (int ni = 0; ni < 4; ni++) {
            int r1 = row0 + wm * 64 + mi * 16 + g;
            int r2 = r1 + 8;
            int col = col0 + wn * 32 + ni * 8 + tig * 2;
            float* ac = acc[mi][ni];
            if (MODE == 0) {
                float* C = (float*)C0v + cOff;
                *(float2*)(C + (ll)r1 * ldc + col) = make_float2(ac[0], ac[1]);
                *(float2*)(C + (ll)r2 * ldc + col) = make_float2(ac[2], ac[3]);
            } else if (MODE == 1) {
                float* C = (float*)C0v + cOff;
                float2 v1, v2;
                v1.x = (col     > r1) ? -1e30f : ac[0] * scale;
                v1.y = (col + 1 > r1) ? -1e30f : ac[1] * scale;
                v2.x = (col     > r2) ? -1e30f : ac[2] * scale;
                v2.y = (col + 1 > r2) ? -1e30f : ac[3] * scale;
                *(float2*)(C + (ll)r1 * ldc + col) = v1;
                *(float2*)(C + (ll)r2 * ldc + col) = v2;
            } else {
                __half* Ch = (__half*)C0v;
                __half* Cl = (__half*)C1v;
                ll b1, b2;
                if (MODE == 3) {
                    b1 = cOff + (ll)r1 * ldc + col;
                    b2 = cOff + (ll)r2 * ldc + col;
                } else {
                    int hg1 = r1 >> 11, s1 = r1 & 2047;
                    int hg2 = r2 >> 11, s2 = r2 & 2047;
                    b1 = cOff + (ll)(hg1 * 512 + (s1 >> 2)) * FH_ + (ll)(s1 & 3) * 2048 + col;
                    b2 = cOff + (ll)(hg2 * 512 + (s2 >> 2)) * FH_ + (ll)(s2 & 3) * 2048 + col;
                }
                *(u32*)(Ch + b1) = pack_hi(ac[0], ac[1]);
                *(u32*)(Ch + b2) = pack_hi(ac[2], ac[3]);
                if (Cl) {
                    *(u32*)(Cl + b1) = pack_lo(ac[0], ac[1]);
                    *(u32*)(Cl + b2) = pack_lo(ac[2], ac[3]);
                }
            }
        }
    }
}

// ============ mega-convert ============
static constexpr ll C_H   = N_H   / 4;
static constexpr ll C_WQ  = C_H   + N_WQ  / 4;
static constexpr ll C_WVT = C_WQ  + N_WVT / 4;
static constexpr ll C_WV  = C_WVT + N_WV  / 4;
static constexpr ll C_U   = C_WV  + N_U   / 4;
static constexpr ll C_WO  = C_U   + N_WO  / 4;

__global__ void convert_all(const float* __restrict__ H,  const float* __restrict__ Wq,
                            const float* __restrict__ WVT, const float* __restrict__ Wv,
                            const float* __restrict__ U,  const float* __restrict__ Wo,
                            __half* __restrict__ Hh, __half* __restrict__ Hl,
                            __half* __restrict__ Wq1, __half* __restrict__ WVT1,
                            __half* __restrict__ Wv1, __half* __restrict__ U1,
                            __half* __restrict__ Wo1)
{
    ll i = (ll)blockIdx.x * blockDim.x + threadIdx.x;
    const ll stride = (ll)gridDim.x * blockDim.x;
    for (; i < C_WO; i += stride) {
        const float* src; __half* dh; __half* dl = nullptr; ll j;
        if (i < C_H)        { src = H;   dh = Hh;   dl = Hl; j = i; }
        else if (i < C_WQ)  { src = Wq;  dh = Wq1;  j = i - C_H; }
        else if (i < C_WVT) { src = WVT; dh = WVT1; j = i - C_WQ; }
        else if (i < C_WV)  { src = Wv;  dh = Wv1;  j = i - C_WVT; }
        else if (i < C_U)   { src = U;   dh = U1;   j = i - C_WV; }
        else                { src = Wo;  dh = Wo1;  j = i - C_U; }
        float4 v = __ldg((const float4*)src + j);
        ((uint2*)dh)[j] = make_uint2(pack_hi(v.x, v.y), pack_hi(v.z, v.w));
        if (dl) ((uint2*)dl)[j] = make_uint2(pack_lo(v.x, v.y), pack_lo(v.z, v.w));
    }
}

// ============ RoPE: fp32 Q/K -> rotated (hi,lo) fp16 ============
__global__ void rope_split(const float* __restrict__ Qf, const float* __restrict__ Kf,
                           const int* __restrict__ pos,
                           __half* __restrict__ Qh, __half* __restrict__ Ql,
                           __half* __restrict__ Kh, __half* __restrict__ Kl)
{
    const int row = blockIdx.x;
    const float p = (float)__ldg(pos + row);
    const ll base = (ll)row * HID_;
    for (int t = threadIdx.x; t < NH_ * 64; t += blockDim.x) {
        int h = t >> 6, d = t & 63;
        float inv = exp2f(-(float)d * (13.287712379549449f / 64.0f));
        float sn, cs;
        sincosf(p * inv, &sn, &cs);
        ll c1 = base + h * 128 + d, c2 = c1 + 64;
        float qx = Qf[c1], qy = Qf[c2];
        float q1 = qx * cs - qy * sn, q2 = qy * cs + qx * sn;
        __half a = __float2half_rn(q1); Qh[c1] = a; Ql[c1] = __float2half_rn(q1 - __half2float(a));
        __half b = __float2half_rn(q2); Qh[c2] = b; Ql[c2] = __float2half_rn(q2 - __half2float(b));
        float kx = Kf[c1], ky = Kf[c2];
        float k1 = kx * cs - ky * sn, k2 = ky * cs + kx * sn;
        __half c = __float2half_rn(k1); Kh[c1] = c; Kl[c1] = __float2half_rn(k1 - __half2float(c));
        __half e = __float2half_rn(k2); Kh[c2] = e; Kl[c2] = __float2half_rn(k2 - __half2float(e));
    }
}

// ============ transpose ============
__global__ void transpose_single(const float* __restrict__ V, __half* __restrict__ Th)
{
    __shared__ float t[32][33];
    const int b = blockIdx.z, s0 = blockIdx.x * 32, n0 = blockIdx.y * 32;
    const int x = threadIdx.x;
    for (int y = threadIdx.y; y < 32; y += 8)
        t[y][x] = __ldg(V + (ll)(b * 2048 + s0 + y) * 2048 + n0 + x);
    __syncthreads();
    for (int yo = threadIdx.y; yo < 32; yo += 8) {
        ll idx = (ll)(b * 2048 + n0 + yo) * 2048 + s0 + x;
        Th[idx] = __float2half_rn(t[x][yo]);
    }
}

// ============ causal-prefix softmax -> single fp16 ============
__global__ void __launch_bounds__(256) softmax_single(const float* __restrict__ Pf,
                                                      __half* __restrict__ Ph)
{
    const ll row = blockIdx.x;
    const int rl = (int)(row & 2047);
    const int nproc = ((rl >> 7) + 1) << 7;
    const float* src = Pf + row * 2048;
    const int tid = threadIdx.x;
    float v[8];
    float m = -1e38f;
    #pragma unroll
    for (int i = 0; i < 8; i++) {
        int c = tid + i * 256;
        v[i] = (c < nproc) ? src[c] : -1e38f;
        m = fmaxf(m, v[i]);
    }
    __shared__ float red[256];
    red[tid] = m; __syncthreads();
    #pragma unroll
    for (int s = 128; s > 0; s >>= 1) {
        if (tid < s) red[tid] = fmaxf(red[tid], red[tid + s]);
        __syncthreads();
    }
    m = red[0];
    __syncthreads();
    float sum = 0.0f;
    #pragma unroll
    for (int i = 0; i < 8; i++) { v[i] = expf(v[i] - m); sum += v[i]; }
    red[tid] = sum; __syncthreads();
    #pragma unroll
    for (int s = 128; s > 0; s >>= 1) {
        if (tid < s) red[tid] += red[tid + s];
        __syncthreads();
    }
    const float inv = 1.0f / red[0];
    #pragma unroll
    for (int i = 0; i < 8; i++) {
        int c = tid + i * 256;
        if (c < nproc)
            Ph[row * 2048 + c] = __float2half_rn(v[i] * inv);
    }
}

// ============ launcher ============
extern "C" void kernel_launch(void* const* d_in, const int* in_sizes, int n_in,
                              void* d_out, int out_size)
{
    const float* H   = (const float*)d_in[0];
    const int*   pos = (const int*)  d_in[2];
    const float* Wq  = (const float*)d_in[3];
    const float* WVT = (const float*)d_in[4];
    const float* U   = (const float*)d_in[5];
    const float* Wv  = (const float*)d_in[6];
    const float* Wo  = (const float*)d_in[7];
    float* out = (float*)d_out;

    const int SMEM1 = 5 * 16384;
    const int SMEM2 = 4 * 24576;
    const int SMEM3 = 3 * 32768;
    cudaFuncSetAttribute((const void*)wgemm<0,2>, cudaFuncAttributeMaxDynamicSharedMemorySize, SMEM2);
    cudaFuncSetAttribute((const void*)wgemm<0,1>, cudaFuncAttributeMaxDynamicSharedMemorySize, SMEM1);
    cudaFuncSetAttribute((const void*)wgemm<1,3>, cudaFuncAttributeMaxDynamicSharedMemorySize, SMEM3);
    cudaFuncSetAttribute((const void*)wgemm<2,1>, cudaFuncAttributeMaxDynamicSharedMemorySize, SMEM1);
    cudaFuncSetAttribute((const void*)wgemm<3,2>, cudaFuncAttributeMaxDynamicSharedMemorySize, SMEM2);

    __half *Hh, *Hl, *Wq1, *WVT1, *Wv1, *U1, *Wo1;
    __half *Qh, *Ql, *Kh, *Kl, *klath, *klatl, *vT1, *Ph, *scrh;
    float *Qf, *Kf, *vlatf, *Pf;
    cudaGetSymbolAddress((void**)&Hh, g_Hh);       cudaGetSymbolAddress((void**)&Hl, g_Hl);
    cudaGetSymbolAddress((void**)&Wq1, g_Wq1);
    cudaGetSymbolAddress((void**)&WVT1, g_WVT1);
    cudaGetSymbolAddress((void**)&Wv1, g_Wv1);
    cudaGetSymbolAddress((void**)&U1, g_U1);
    cudaGetSymbolAddress((void**)&Wo1, g_Wo1);
    cudaGetSymbolAddress((void**)&Qf, g_Qf);       cudaGetSymbolAddress((void**)&Kf, g_Kf);
    cudaGetSymbolAddress((void**)&Qh, g_Qh);       cudaGetSymbolAddress((void**)&Ql, g_Ql);
    cudaGetSymbolAddress((void**)&Kh, g_Kh);       cudaGetSymbolAddress((void**)&Kl, g_Kl);
    cudaGetSymbolAddress((void**)&klath, g_klath); cudaGetSymbolAddress((void**)&klatl, g_klatl);
    cudaGetSymbolAddress((void**)&vlatf, g_vlatf);
    cudaGetSymbolAddress((void**)&vT1, g_vT1);
    cudaGetSymbolAddress((void**)&Pf, g_Pf);
    cudaGetSymbolAddress((void**)&Ph, g_Ph);
    cudaGetSymbolAddress((void**)&scrh, g_scrh);

    // our launch 0: ALL converts in one kernel
    convert_all<<<8192, 256>>>(H, Wq, WVT, Wv, U, Wo, Hh, Hl, Wq1, WVT1, Wv1, U1, Wo1);

    // our launch 1: klat = H @ WVT^T (4096x2048) -> fp16 hi/lo
    wgemm<3,2><<<dim3(16, 32, 1), 256, SMEM2>>>(
        Hh, Hl, WVT1, nullptr, klath, klatl, HID_, HID_, HID_, 2048,
        0, 0, 0, 0, 0, 0, 1, 1.0f);
    // our launch 2: vlat = H @ Wv^T (4096x2048) -> fp32
    wgemm<0,2><<<dim3(16, 32, 1), 256, SMEM2>>>(
        Hh, Hl, Wv1, nullptr, vlatf, nullptr, HID_, HID_, HID_, 2048,
        0, 0, 0, 0, 0, 0, 1, 1.0f);
    // our launch 3: Q = H @ Wq^T (4096x4096, K=4096) -> fp32
    wgemm<0,2><<<dim3(32, 32, 1), 256, SMEM2>>>(
        Hh, Hl, Wq1, nullptr, Qf, nullptr, HID_, HID_, HID_, HID_,
        0, 0, 0, 0, 0, 0, 1, 1.0f);
    // our launch 4: K recon per (b,g): (2048x512, K=256) -> fp32
    wgemm<0,2><<<dim3(4, 16, 16), 256, SMEM2>>>(
        klath, klatl, U1, nullptr, Kf, nullptr, RK_, 2048, 2048, HID_,
        (ll)S_ * 2048, RK_, 0, RK_, (ll)S_ * HID_, 512, G_, 1.0f);
    // our launch 5: vT transpose
    transpose_single<<<dim3(64, 64, B_), dim3(32, 8)>>>(vlatf, vT1);
    // our launch 6: RoPE -> hi/lo fp16 Q, K
    rope_split<<<B_ * S_, 256>>>(Qf, Kf, pos, Qh, Ql, Kh, Kl);
    // our launch 7: scores per (b,h): (2048x2048, K=128), 3-term, scale+causal -> fp32
    wgemm<1,3><<<dim3(16, 16, 64), 256, SMEM3>>>(
        Qh, Ql, Kh, Kl, Pf, nullptr, 128, HID_, HID_, S_,
        (ll)S_ * HID_, 128, (ll)S_ * HID_, 128,
        (ll)NH_ * S_ * S_, (ll)S_ * S_, NH_, 0.08838834764831845f);
    // our launch 8: softmax -> single fp16 probs (causal prefix only)
    softmax_single<<<B_ * NH_ * S_, 256>>>(Pf, Ph);
    // our launch 9: AV per (b,g): (8192x256, K truncated), P single fp16 -> scrambled fp16
    wgemm<2,1><<<dim3(2, 64, 16), 256, SMEM1>>>(
        Ph, nullptr, vT1, nullptr, scrh, nullptr, S_, S_, S_, 0,
        (ll)NH_ * S_ * S_, (ll)4 * S_ * S_,
        (ll)2048 * 2048, (ll)FGD_ * S_,
        (ll)S_ * FH_, FGD_, G_, 1.0f);
    // our launch 10: out = scr @ Wo^T (4096x4096, K=8192), A single fp16
    wgemm<0,1><<<dim3(32, 32, 1), 256, SMEM1>>>(
        scrh, nullptr, Wo1, nullptr, out, nullptr, FH_, FH_, FH_, HID_,
        0, 0, 0, 0, 0, 0, 1, 1.0f);
}

// round 15
// speedup vs baseline: 1.3660x; 1.0213x over previous
#include <cuda_runtime.h>
#include <cuda_fp16.h>
#include <stdint.h>
#include <math.h>

typedef long long ll;
typedef unsigned int u32;
typedef unsigned long long u64;

static constexpr int B_   = 2;
static constexpr int S_   = 2048;
static constexpr int HID_ = 4096;
static constexpr int NH_  = 32;
static constexpr int G_   = 8;
static constexpr int RK_  = 256;
static constexpr int FGD_ = 256;
static constexpr int FH_  = 8192;

static constexpr ll N_H   = (ll)B_ * S_ * HID_;
static constexpr ll N_WQ  = (ll)HID_ * HID_;
static constexpr ll N_WVT = (ll)(G_*RK_) * HID_;
static constexpr ll N_WV  = (ll)(G_*FGD_) * HID_;
static constexpr ll N_U   = (ll)512 * (G_*RK_);
static constexpr ll N_WO  = (ll)HID_ * FH_;
static constexpr ll N_LAT = (ll)B_ * S_ * (G_*RK_);
static constexpr ll N_P   = (ll)B_ * NH_ * S_ * S_;
static constexpr ll N_SCR = (ll)B_ * S_ * FH_;

__device__ __half g_Hh[N_H],     g_Hl[N_H];
__device__ __half g_Wq1[N_WQ];
__device__ __half g_WVT1[N_WVT];
__device__ __half g_Wv1[N_WV];
__device__ __half g_U1[N_U];
__device__ __half g_Wo1[N_WO];
__device__ float  g_Qf[N_H],    g_Kf[N_H];
__device__ __half g_Qh[N_H], g_Ql[N_H], g_Kh[N_H], g_Kl[N_H];
__device__ __half g_klath[N_LAT], g_klatl[N_LAT];
__device__ __half g_vlath[N_LAT];
__device__ __half g_vT1[N_LAT];
__device__ float  g_Pf[N_P];
__device__ __half g_Ph[N_P];
__device__ __half g_scrh[N_SCR];

// ---------------- PTX helpers ----------------
__device__ __forceinline__ u32 smem_u32(const void* p) {
    u32 a;
    asm("{ .reg .u64 t; cvta.to.shared.u64 t, %1; cvt.u32.u64 %0, t; }" : "=r"(a) : "l"(p));
    return a;
}
__device__ __forceinline__ void cp16(u32 dst, const void* src) {
    asm volatile("cp.async.cg.shared.global [%0], [%1], 16;" :: "r"(dst), "l"(src));
}
__device__ __forceinline__ void cp_commit() { asm volatile("cp.async.commit_group;" ::: "memory"); }
template<int N>
__device__ __forceinline__ void cp_waitN() { asm volatile("cp.async.wait_group %0;" :: "n"(N) : "memory"); }
__device__ __forceinline__ void ldsm4(u32* r, u32 addr) {
    asm volatile("ldmatrix.sync.aligned.m8n8.x4.shared.b16 {%0,%1,%2,%3}, [%4];"
                 : "=r"(r[0]), "=r"(r[1]), "=r"(r[2]), "=r"(r[3]) : "r"(addr));
}
__device__ __forceinline__ void mma16816(float* d, const u32* a, const u32* b) {
    asm volatile("mma.sync.aligned.m16n8k16.row.col.f32.f16.f16.f32 "
                 "{%0,%1,%2,%3}, {%4,%5,%6,%7}, {%8,%9}, {%0,%1,%2,%3};"
                 : "+f"(d[0]), "+f"(d[1]), "+f"(d[2]), "+f"(d[3])
                 : "r"(a[0]), "r"(a[1]), "r"(a[2]), "r"(a[3]), "r"(b[0]), "r"(b[1]));
}
__device__ __forceinline__ u32 pack_hi(float v0, float v1) {
    __half2 p = __halves2half2(__float2half_rn(v0), __float2half_rn(v1));
    return *(u32*)&p;
}
__device__ __forceinline__ u32 pack_lo(float v0, float v1) {
    __half h0 = __float2half_rn(v0), h1 = __float2half_rn(v1);
    __half2 p = __halves2half2(__float2half_rn(v0 - __half2float(h0)),
                               __float2half_rn(v1 - __half2float(h1)));
    return *(u32*)&p;
}
// conflict-free 16B-slot swizzle for 64B rows
__device__ __forceinline__ u32 swz(int r, int c) {
    return (u32)(r * 64 + (((c ^ ((r >> 1) & 3)) & 3) << 4));
}

// ======================================================================================
// Generic warp-MMA fp16 GEMM (unchanged R13 engine): CTA 128x128, 8 warps, 2 CTAs/SM,
// single-barrier multistage. PREC/MODE semantics as before.
// ======================================================================================
template<int MODE, int PREC>
__global__ void __launch_bounds__(256, 2)
wgemm(const __half* __restrict__ Ah, const __half* __restrict__ Al,
      const __half* __restrict__ Bh, const __half* __restrict__ Bl,
      void* C0v, void* C1v, int K, int lda, int ldb, int ldc,
      ll aSo, ll aSi, ll bSo, ll bSi, ll cSo, ll cSi, int ziCount, float scale)
{
    constexpr int STAGE  = (PREC == 3) ? 32768 : (PREC == 2 ? 24576 : 16384);
    constexpr int NSTAGE = (PREC == 3) ? 3 : (PREC == 2 ? 4 : 5);
    constexpr int BOFF   = (PREC >= 2) ? 16384 : 8192;
    const int row0 = blockIdx.y * 128;
    const int col0 = blockIdx.x * 128;
    if (MODE == 1 && col0 > row0 + 127) return;

    const int zo = blockIdx.z / ziCount, zi = blockIdx.z % ziCount;
    const ll aOff = (ll)zo * aSo + (ll)zi * aSi + (ll)row0 * lda;
    const ll bOff = (ll)zo * bSo + (ll)zi * bSi + (ll)col0 * ldb;
    Ah += aOff; Bh += bOff;
    if (PREC >= 2) Al += aOff;
    if (PREC == 3) Bl += bOff;
    const ll cOff = (ll)zo * cSo + (ll)zi * cSi;

    int Keff = K;
    if (MODE == 2) { int lim = (row0 & 2047) + 128; if (lim < Keff) Keff = lim; }
    const int nK = Keff >> 5;

    extern __shared__ char sm[];
    const u32 sb = smem_u32(sm);
    const int tid = threadIdx.x, wid = tid >> 5, lane = tid & 31;
    const int wm = wid >> 2, wn = wid & 3;

    float acc[4][4][4];
    #pragma unroll
    for (int a = 0; a < 4; a++)
        #pragma unroll
        for (int b = 0; b < 4; b++)
            #pragma unroll
            for (int c = 0; c < 4; c++) acc[a][b][c] = 0.0f;

    auto load_stage = [&](int kt) {
        const u32 sbase = sb + (kt % NSTAGE) * STAGE;
        const int k0 = kt << 5;
        constexpr int NCHUNK = (PREC == 3) ? 8 : (PREC == 2 ? 6 : 4);
        constexpr int NA = (PREC >= 2) ? 1024 : 512;
        #pragma unroll
        for (int i = 0; i < NCHUNK; i++) {
            int idx = tid + i * 256;
            if (idx < NA) {
                int sub = (PREC >= 2) ? (idx >> 9) : 0;
                int m = (PREC >= 2) ? (idx & 511) : idx;
                int r = m >> 2, c = m & 3;
                u32 d = sbase + sub * 8192 + swz(r, c);
                const __half* src = sub ? Al : Ah;
                cp16(d, src + (ll)r * lda + k0 + c * 8);
            } else {
                int j = idx - NA;
                int sub = (PREC == 3) ? (j >> 9) : 0;
                int m = (PREC == 3) ? (j & 511) : j;
                int r = m >> 2, c = m & 3;
                u32 d = sbase + BOFF + sub * 8192 + swz(r, c);
                const __half* src = (PREC == 3 && sub) ? Bl : Bh;
                cp16(d, src + (ll)r * ldb + k0 + c * 8);
            }
        }
    };

    #pragma unroll
    for (int s = 0; s < NSTAGE - 1; s++) {
        if (s == 0 || s < nK) load_stage(s);
        cp_commit();
    }

    for (int kt = 0; kt < nK; kt++) {
        cp_waitN<NSTAGE - 2>();
        __syncthreads();
        if (kt + NSTAGE - 1 < nK) load_stage(kt + NSTAGE - 1);
        cp_commit();

        const u32 abase = sb + (kt % NSTAGE) * STAGE;
        #pragma unroll
        for (int kk = 0; kk < 2; kk++) {
            u32 aH[4][4], aL[4][4];
            #pragma unroll
            for (int mi = 0; mi < 4; mi++) {
                int row = wm * 64 + mi * 16 + ((lane >> 3) & 1) * 8 + (lane & 7);
                int kb4 = kk * 2 + ((lane >> 4) & 1);
                u32 ad = abase + swz(row, kb4);
                ldsm4(aH[mi], ad);
                if (PREC >= 2) ldsm4(aL[mi], ad + 8192);
            }
            #pragma unroll
            for (int nj = 0; nj < 2; nj++) {
                int n = wn * 32 + nj * 16 + ((lane >> 4) & 1) * 8 + (lane & 7);
                int kb4 = kk * 2 + ((lane >> 3) & 1);
                u32 bd = abase + BOFF + swz(n, kb4);
                u32 tH[4];
                ldsm4(tH, bd);
                if (PREC == 3) {
                    u32 tL[4];
                    ldsm4(tL, bd + 8192);
                    #pragma unroll
                    for (int mi = 0; mi < 4; mi++) {
                        mma16816(acc[mi][nj*2],   aH[mi], tH);
                        mma16816(acc[mi][nj*2],   aH[mi], tL);
                        mma16816(acc[mi][nj*2],   aL[mi], tH);
                        mma16816(acc[mi][nj*2+1], aH[mi], tH + 2);
                        mma16816(acc[mi][nj*2+1], aH[mi], tL + 2);
                        mma16816(acc[mi][nj*2+1], aL[mi], tH + 2);
                    }
                } else if (PREC == 2) {
                    #pragma unroll
                    for (int mi = 0; mi < 4; mi++) {
                        mma16816(acc[mi][nj*2],   aH[mi], tH);
                        mma16816(acc[mi][nj*2],   aL[mi], tH);
                        mma16816(acc[mi][nj*2+1], aH[mi], tH + 2);
                        mma16816(acc[mi][nj*2+1], aL[mi], tH + 2);
                    }
                } else {
                    #pragma unroll
                    for (int mi = 0; mi < 4; mi++) {
                        mma16816(acc[mi][nj*2],   aH[mi], tH);
                        mma16816(acc[mi][nj*2+1], aH[mi], tH + 2);
                    }
                }
            }
        }
    }

    // ---- epilogue ----
    const int g = lane >> 2, tig = lane & 3;
    #pragma unroll
    for (int mi = 0; mi < 4; mi++) {
        #pragma unroll
        for (int ni = 0; ni < 4; ni++) {
            int r1 = row0 + wm * 64 + mi * 16 + g;
            int r2 = r1 + 8;
            int col = col0 + wn * 32 + ni * 8 + tig * 2;
            float* ac = acc[mi][ni];
            if (MODE == 0) {
                float* C = (float*)C0v + cOff;
                *(float2*)(C + (ll)r1 * ldc + col) = make_float2(ac[0], ac[1]);
                *(float2*)(C + (ll)r2 * ldc + col) = make_float2(ac[2], ac[3]);
            } else if (MODE == 1) {
                float* C = (float*)C0v + cOff;
                float2 v1, v2;
                v1.x = (col     > r1) ? -1e30f : ac[0] * scale;
                v1.y = (col + 1 > r1) ? -1e30f : ac[1] * scale;
                v2.x = (col     > r2) ? -1e30f : ac[2] * scale;
                v2.y = (col + 1 > r2) ? -1e30f : ac[3] * scale;
                *(float2*)(C + (ll)r1 * ldc + col) = v1;
                *(float2*)(C + (ll)r2 * ldc + col) = v2;
            } else {
                __half* Ch = (__half*)C0v;
                __half* Cl = (__half*)C1v;
                ll b1, b2;
                if (MODE == 3) {
                    b1 = cOff + (ll)r1 * ldc + col;
                    b2 = cOff + (ll)r2 * ldc + col;
                } else {
                    int hg1 = r1 >> 11, s1 = r1 & 2047;
                    int hg2 = r2 >> 11, s2 = r2 & 2047;
                    b1 = cOff + (ll)(hg1 * 512 + (s1 >> 2)) * FH_ + (ll)(s1 & 3) * 2048 + col;
                    b2 = cOff + (ll)(hg2 * 512 + (s2 >> 2)) * FH_ + (ll)(s2 & 3) * 2048 + col;
                }
                *(u32*)(Ch + b1) = pack_hi(ac[0], ac[1]);
                *(u32*)(Ch + b2) = pack_hi(ac[2], ac[3]);
                if (Cl) {
                    *(u32*)(Cl + b1) = pack_lo(ac[0], ac[1]);
                    *(u32*)(Cl + b2) = pack_lo(ac[2], ac[3]);
                }
            }
        }
    }
}

// ======================================================================================
// Fused projection GEMM: one launch computes Q (fp32), klat (fp16 hi/lo), vlat (fp16).
// grid (64, 32): x<32 -> Q, x<48 -> klat, else vlat. PREC2 engine, K=4096.
// ======================================================================================
__global__ void __launch_bounds__(256, 2)
wgemm_proj(const __half* __restrict__ Ah, const __half* __restrict__ Al,
           const __half* __restrict__ Bq, const __half* __restrict__ Bkvt,
           const __half* __restrict__ Bv,
           float* __restrict__ Qf, __half* __restrict__ klath,
           __half* __restrict__ klatl, __half* __restrict__ vlath)
{
    constexpr int STAGE = 24576, NSTAGE = 4, BOFF = 16384;
    const int x = blockIdx.x;
    int seg, xl;
    const __half* Bh;
    if (x < 32)      { seg = 0; xl = x;      Bh = Bq; }
    else if (x < 48) { seg = 1; xl = x - 32; Bh = Bkvt; }
    else             { seg = 2; xl = x - 48; Bh = Bv; }
    const int row0 = blockIdx.y * 128;
    const int col0 = xl * 128;
    Ah += (ll)row0 * HID_;
    Al += (ll)row0 * HID_;
    Bh += (ll)col0 * HID_;

    extern __shared__ char sm[];
    const u32 sb = smem_u32(sm);
    const int tid = threadIdx.x, wid = tid >> 5, lane = tid & 31;
    const int wm = wid >> 2, wn = wid & 3;

    float acc[4][4][4];
    #pragma unroll
    for (int a = 0; a < 4; a++)
        #pragma unroll
        for (int b = 0; b < 4; b++)
            #pragma unroll
            for (int c = 0; c < 4; c++) acc[a][b][c] = 0.0f;

    auto load_stage = [&](int kt) {
        const u32 sbase = sb + (kt % NSTAGE) * STAGE;
        const int k0 = kt << 5;
        #pragma unroll
        for (int i = 0; i < 6; i++) {
            int idx = tid + i * 256;
            if (idx < 1024) {
                int sub = idx >> 9;
                int m = idx & 511;
                int r = m >> 2, c = m & 3;
                u32 d = sbase + sub * 8192 + swz(r, c);
                const __half* src = sub ? Al : Ah;
                cp16(d, src + (ll)r * HID_ + k0 + c * 8);
            } else {
                int m = idx - 1024;
                int r = m >> 2, c = m & 3;
                cp16(sbase + BOFF + swz(r, c), Bh + (ll)r * HID_ + k0 + c * 8);
            }
        }
    };

    #pragma unroll
    for (int s = 0; s < NSTAGE - 1; s++) { load_stage(s); cp_commit(); }

    const int nK = HID_ >> 5;   // 128
    for (int kt = 0; kt < nK; kt++) {
        cp_waitN<NSTAGE - 2>();
        __syncthreads();
        if (kt + NSTAGE - 1 < nK) load_stage(kt + NSTAGE - 1);
        cp_commit();

        const u32 abase = sb + (kt % NSTAGE) * STAGE;
        #pragma unroll
        for (int kk = 0; kk < 2; kk++) {
            u32 aH[4][4], aL[4][4];
            #pragma unroll
            for (int mi = 0; mi < 4; mi++) {
                int row = wm * 64 + mi * 16 + ((lane >> 3) & 1) * 8 + (lane & 7);
                int kb4 = kk * 2 + ((lane >> 4) & 1);
                u32 ad = abase + swz(row, kb4);
                ldsm4(aH[mi], ad);
                ldsm4(aL[mi], ad + 8192);
            }
            #pragma unroll
            for (int nj = 0; nj < 2; nj++) {
                int n = wn * 32 + nj * 16 + ((lane >> 4) & 1) * 8 + (lane & 7);
                int kb4 = kk * 2 + ((lane >> 3) & 1);
                u32 tH[4];
                ldsm4(tH, abase + BOFF + swz(n, kb4));
                #pragma unroll
                for (int mi = 0; mi < 4; mi++) {
                    mma16816(acc[mi][nj*2],   aH[mi], tH);
                    mma16816(acc[mi][nj*2],   aL[mi], tH);
                    mma16816(acc[mi][nj*2+1], aH[mi], tH + 2);
                    mma16816(acc[mi][nj*2+1], aL[mi], tH + 2);
                }
            }
        }
    }

    const int g = lane >> 2, tig = lane & 3;
    #pragma unroll
    for (int mi = 0; mi < 4; mi++) {
        #pragma unroll
        for (int ni = 0; ni < 4; ni++) {
            int r1 = row0 + wm * 64 + mi * 16 + g;
            int r2 = r1 + 8;
            int col = col0 + wn * 32 + ni * 8 + tig * 2;
            float* ac = acc[mi][ni];
            if (seg == 0) {
                *(float2*)(Qf + (ll)r1 * HID_ + col) = make_float2(ac[0], ac[1]);
                *(float2*)(Qf + (ll)r2 * HID_ + col) = make_float2(ac[2], ac[3]);
            } else if (seg == 1) {
                ll b1 = (ll)r1 * 2048 + col, b2 = (ll)r2 * 2048 + col;
                *(u32*)(klath + b1) = pack_hi(ac[0], ac[1]);
                *(u32*)(klath + b2) = pack_hi(ac[2], ac[3]);
                *(u32*)(klatl + b1) = pack_lo(ac[0], ac[1]);
                *(u32*)(klatl + b2) = pack_lo(ac[2], ac[3]);
            } else {
                ll b1 = (ll)r1 * 2048 + col, b2 = (ll)r2 * 2048 + col;
                *(u32*)(vlath + b1) = pack_hi(ac[0], ac[1]);
                *(u32*)(vlath + b2) = pack_hi(ac[2], ac[3]);
            }
        }
    }
}

// ============ mega-convert ============
static constexpr ll C_H   = N_H   / 4;
static constexpr ll C_WQ  = C_H   + N_WQ  / 4;
static constexpr ll C_WVT = C_WQ  + N_WVT / 4;
static constexpr ll C_WV  = C_WVT + N_WV  / 4;
static constexpr ll C_U   = C_WV  + N_U   / 4;
static constexpr ll C_WO  = C_U   + N_WO  / 4;

__global__ void convert_all(const float* __restrict__ H,  const float* __restrict__ Wq,
                            const float* __restrict__ WVT, const float* __restrict__ Wv,
                            const float* __restrict__ U,  const float* __restrict__ Wo,
                            __half* __restrict__ Hh, __half* __restrict__ Hl,
                            __half* __restrict__ Wq1, __half* __restrict__ WVT1,
                            __half* __restrict__ Wv1, __half* __restrict__ U1,
                            __half* __restrict__ Wo1)
{
    ll i = (ll)blockIdx.x * blockDim.x + threadIdx.x;
    const ll stride = (ll)gridDim.x * blockDim.x;
    for (; i < C_WO; i += stride) {
        const float* src; __half* dh; __half* dl = nullptr; ll j;
        if (i < C_H)        { src = H;   dh = Hh;   dl = Hl; j = i; }
        else if (i < C_WQ)  { src = Wq;  dh = Wq1;  j = i - C_H; }
        else if (i < C_WVT) { src = WVT; dh = WVT1; j = i - C_WQ; }
        else if (i < C_WV)  { src = Wv;  dh = Wv1;  j = i - C_WVT; }
        else if (i < C_U)   { src = U;   dh = U1;   j = i - C_WV; }
        else                { src = Wo;  dh = Wo1;  j = i - C_U; }
        float4 v = __ldg((const float4*)src + j);
        ((uint2*)dh)[j] = make_uint2(pack_hi(v.x, v.y), pack_hi(v.z, v.w));
        if (dl) ((uint2*)dl)[j] = make_uint2(pack_lo(v.x, v.y), pack_lo(v.z, v.w));
    }
}

// ============ RoPE ============
__global__ void rope_split(const float* __restrict__ Qf, const float* __restrict__ Kf,
                           const int* __restrict__ pos,
                           __half* __restrict__ Qh, __half* __restrict__ Ql,
                           __half* __restrict__ Kh, __half* __restrict__ Kl)
{
    const int row = blockIdx.x;
    const float p = (float)__ldg(pos + row);
    const ll base = (ll)row * HID_;
    for (int t = threadIdx.x; t < NH_ * 64; t += blockDim.x) {
        int h = t >> 6, d = t & 63;
        float inv = exp2f(-(float)d * (13.287712379549449f / 64.0f));
        float sn, cs;
        sincosf(p * inv, &sn, &cs);
        ll c1 = base + h * 128 + d, c2 = c1 + 64;
        float qx = Qf[c1], qy = Qf[c2];
        float q1 = qx * cs - qy * sn, q2 = qy * cs + qx * sn;
        __half a = __float2half_rn(q1); Qh[c1] = a; Ql[c1] = __float2half_rn(q1 - __half2float(a));
        __half b = __float2half_rn(q2); Qh[c2] = b; Ql[c2] = __float2half_rn(q2 - __half2float(b));
        float kx = Kf[c1], ky = Kf[c2];
        float k1 = kx * cs - ky * sn, k2 = ky * cs + kx * sn;
        __half c = __float2half_rn(k1); Kh[c1] = c; Kl[c1] = __float2half_rn(k1 - __half2float(c));
        __half e = __float2half_rn(k2); Kh[c2] = e; Kl[c2] = __float2half_rn(k2 - __half2float(e));
    }
}

// ============ transpose (fp16 in, fp16 out) ============
__global__ void transpose_single(const __half* __restrict__ V, __half* __restrict__ Th)
{
    __shared__ float t[32][33];
    const int b = blockIdx.z, s0 = blockIdx.x * 32, n0 = blockIdx.y * 32;
    const int x = threadIdx.x;
    for (int y = threadIdx.y; y < 32; y += 8)
        t[y][x] = __half2float(__ldg(V + (ll)(b * 2048 + s0 + y) * 2048 + n0 + x));
    __syncthreads();
    for (int yo = threadIdx.y; yo < 32; yo += 8) {
        ll idx = (ll)(b * 2048 + n0 + yo) * 2048 + s0 + x;
        Th[idx] = __float2half_rn(t[x][yo]);
    }
}

// ============ causal-prefix softmax -> single fp16 ============
__global__ void __launch_bounds__(256) softmax_single(const float* __restrict__ Pf,
                                                      __half* __restrict__ Ph)
{
    const ll row = blockIdx.x;
    const int rl = (int)(row & 2047);
    const int nproc = ((rl >> 7) + 1) << 7;
    const float* src = Pf + row * 2048;
    const int tid = threadIdx.x;
    float v[8];
    float m = -1e38f;
    #pragma unroll
    for (int i = 0; i < 8; i++) {
        int c = tid + i * 256;
        v[i] = (c < nproc) ? src[c] : -1e38f;
        m = fmaxf(m, v[i]);
    }
    __shared__ float red[256];
    red[tid] = m; __syncthreads();
    #pragma unroll
    for (int s = 128; s > 0; s >>= 1) {
        if (tid < s) red[tid] = fmaxf(red[tid], red[tid + s]);
        __syncthreads();
    }
    m = red[0];
    __syncthreads();
    float sum = 0.0f;
    #pragma unroll
    for (int i = 0; i < 8; i++) { v[i] = expf(v[i] - m); sum += v[i]; }
    red[tid] = sum; __syncthreads();
    #pragma unroll
    for (int s = 128; s > 0; s >>= 1) {
        if (tid < s) red[tid] += red[tid + s];
        __syncthreads();
    }
    const float inv = 1.0f / red[0];
    #pragma unroll
    for (int i = 0; i < 8; i++) {
        int c = tid + i * 256;
        if (c < nproc)
            Ph[row * 2048 + c] = __float2half_rn(v[i] * inv);
    }
}

// ============ launcher ============
extern "C" void kernel_launch(void* const* d_in, const int* in_sizes, int n_in,
                              void* d_out, int out_size)
{
    const float* H   = (const float*)d_in[0];
    const int*   pos = (const int*)  d_in[2];
    const float* Wq  = (const float*)d_in[3];
    const float* WVT = (const float*)d_in[4];
    const float* U   = (const float*)d_in[5];
    const float* Wv  = (const float*)d_in[6];
    const float* Wo  = (const float*)d_in[7];
    float* out = (float*)d_out;

    const int SMEM1 = 5 * 16384;
    const int SMEM2 = 4 * 24576;
    const int SMEM3 = 3 * 32768;
    cudaFuncSetAttribute((const void*)wgemm_proj,  cudaFuncAttributeMaxDynamicSharedMemorySize, SMEM2);
    cudaFuncSetAttribute((const void*)wgemm<0,2>, cudaFuncAttributeMaxDynamicSharedMemorySize, SMEM2);
    cudaFuncSetAttribute((const void*)wgemm<0,1>, cudaFuncAttributeMaxDynamicSharedMemorySize, SMEM1);
    cudaFuncSetAttribute((const void*)wgemm<1,3>, cudaFuncAttributeMaxDynamicSharedMemorySize, SMEM3);
    cudaFuncSetAttribute((const void*)wgemm<2,1>, cudaFuncAttributeMaxDynamicSharedMemorySize, SMEM1);

    __half *Hh, *Hl, *Wq1, *WVT1, *Wv1, *U1, *Wo1;
    __half *Qh, *Ql, *Kh, *Kl, *klath, *klatl, *vlath, *vT1, *Ph, *scrh;
    float *Qf, *Kf, *Pf;
    cudaGetSymbolAddress((void**)&Hh, g_Hh);       cudaGetSymbolAddress((void**)&Hl, g_Hl);
    cudaGetSymbolAddress((void**)&Wq1, g_Wq1);
    cudaGetSymbolAddress((void**)&WVT1, g_WVT1);
    cudaGetSymbolAddress((void**)&Wv1, g_Wv1);
    cudaGetSymbolAddress((void**)&U1, g_U1);
    cudaGetSymbolAddress((void**)&Wo1, g_Wo1);
    cudaGetSymbolAddress((void**)&Qf, g_Qf);       cudaGetSymbolAddress((void**)&Kf, g_Kf);
    cudaGetSymbolAddress((void**)&Qh, g_Qh);       cudaGetSymbolAddress((void**)&Ql, g_Ql);
    cudaGetSymbolAddress((void**)&Kh, g_Kh);       cudaGetSymbolAddress((void**)&Kl, g_Kl);
    cudaGetSymbolAddress((void**)&klath, g_klath); cudaGetSymbolAddress((void**)&klatl, g_klatl);
    cudaGetSymbolAddress((void**)&vlath, g_vlath);
    cudaGetSymbolAddress((void**)&vT1, g_vT1);
    cudaGetSymbolAddress((void**)&Pf, g_Pf);
    cudaGetSymbolAddress((void**)&Ph, g_Ph);
    cudaGetSymbolAddress((void**)&scrh, g_scrh);

    // 0: all fp32 -> fp16 conversions
    convert_all<<<8192, 256>>>(H, Wq, WVT, Wv, U, Wo, Hh, Hl, Wq1, WVT1, Wv1, U1, Wo1);
    // 1: fused projections: Q (fp32) + klat (hi/lo) + vlat (fp16), one launch
    wgemm_proj<<<dim3(64, 32, 1), 256, SMEM2>>>(
        Hh, Hl, Wq1, WVT1, Wv1, Qf, klath, klatl, vlath);
    // 2: vT transpose (fp16 -> fp16)
    transpose_single<<<dim3(64, 64, B_), dim3(32, 8)>>>(vlath, vT1);
    // 3: K recon per (b,g): (2048x512, K=256) -> fp32
    wgemm<0,2><<<dim3(4, 16, 16), 256, SMEM2>>>(
        klath, klatl, U1, nullptr, Kf, nullptr, RK_, 2048, 2048, HID_,
        (ll)S_ * 2048, RK_, 0, RK_, (ll)S_ * HID_, 512, G_, 1.0f);
    // 4: RoPE -> hi/lo fp16 Q, K
    rope_split<<<B_ * S_, 256>>>(Qf, Kf, pos, Qh, Ql, Kh, Kl);
    // 5: scores per (b,h): (2048x2048, K=128), 3-term, scale+causal -> fp32
    wgemm<1,3><<<dim3(16, 16, 64), 256, SMEM3>>>(
        Qh, Ql, Kh, Kl, Pf, nullptr, 128, HID_, HID_, S_,
        (ll)S_ * HID_, 128, (ll)S_ * HID_, 128,
        (ll)NH_ * S_ * S_, (ll)S_ * S_, NH_, 0.08838834764831845f);
    // 6: softmax -> single fp16 probs (causal prefix only)
    softmax_single<<<B_ * NH_ * S_, 256>>>(Pf, Ph);
    // 7: AV per (b,g): (8192x256, K truncated), P single fp16 -> scrambled fp16
    wgemm<2,1><<<dim3(2, 64, 16), 256, SMEM1>>>(
        Ph, nullptr, vT1, nullptr, scrh, nullptr, S_, S_, S_, 0,
        (ll)NH_ * S_ * S_, (ll)4 * S_ * S_,
        (ll)2048 * 2048, (ll)FGD_ * S_,
        (ll)S_ * FH_, FGD_, G_, 1.0f);
    // 8: out = scr @ Wo^T (4096x4096, K=8192), A single fp16
    wgemm<0,1><<<dim3(32, 32, 1), 256, SMEM1>>>(
        scrh, nullptr, Wo1, nullptr, out, nullptr, FH_, FH_, FH_, HID_,
        0, 0, 0, 0, 0, 0, 1, 1.0f);
}